// round 1
// baseline (speedup 1.0000x reference)
#include <cuda_runtime.h>
#include <cuda_bf16.h>
#include <math.h>

// Problem constants
#define BB  8
#define SS  1024
#define EE  1024
#define HH  16
#define DD  64
#define FFF 4096
#define MM  (BB*SS)          // 8192 rows

// ---------------- scratch (static device globals; no cudaMalloc allowed) ----
__device__ float g_xn  [(long long)MM*EE];        // 32 MB
__device__ float g_qkv [(long long)MM*3*EE];      // 96 MB
__device__ float g_sc  [(long long)BB*HH*SS*SS];  // 512 MB
__device__ float g_ctx [(long long)MM*EE];        // 32 MB
__device__ float g_x1  [(long long)MM*EE];        // 32 MB
__device__ float g_h   [(long long)MM*FFF];       // 128 MB
__device__ float g_Wqkv[(long long)EE*3*EE];      // 12 MB
__device__ float g_bqkv[3*EE];

// ---------------- weight repack: Wq/Wk/Wv [H,E,D] -> Wqkv [E, 3E] ----------
__global__ void repack_k(const float* __restrict__ Wq, const float* __restrict__ Wk,
                         const float* __restrict__ Wv,
                         const float* __restrict__ bq, const float* __restrict__ bk,
                         const float* __restrict__ bv,
                         float* __restrict__ Wqkv, float* __restrict__ bqkv) {
    int idx = blockIdx.x * blockDim.x + threadIdx.x;
    const int total = HH * EE * DD;
    if (idx < total) {
        int h = idx / (EE * DD);
        int e = (idx / DD) % EE;
        int d = idx % DD;
        int col = h * DD + d;
        long long base = (long long)e * (3 * EE);
        Wqkv[base + col]          = Wq[idx];
        Wqkv[base + EE + col]     = Wk[idx];
        Wqkv[base + 2 * EE + col] = Wv[idx];
    }
    if (idx < EE) {   // bq[h,d] contiguous == col order
        bqkv[idx]          = bq[idx];
        bqkv[EE + idx]     = bk[idx];
        bqkv[2 * EE + idx] = bv[idx];
    }
}

// ---------------- layernorm: one block per row of 1024 ---------------------
__global__ void layernorm_k(const float* __restrict__ x, const float* __restrict__ g,
                            const float* __restrict__ b, float* __restrict__ y) {
    const float4* px = reinterpret_cast<const float4*>(x) + (long long)blockIdx.x * 256;
    float4*       py = reinterpret_cast<float4*>(y)       + (long long)blockIdx.x * 256;
    int tid = threadIdx.x;                // 256 threads, 4 floats each
    float4 v = px[tid];
    float s  = v.x + v.y + v.z + v.w;
    float sq = v.x*v.x + v.y*v.y + v.z*v.z + v.w*v.w;
    __shared__ float rs[8], rq[8];
    #pragma unroll
    for (int o = 16; o; o >>= 1) {
        s  += __shfl_xor_sync(~0u, s,  o);
        sq += __shfl_xor_sync(~0u, sq, o);
    }
    if ((tid & 31) == 0) { rs[tid >> 5] = s; rq[tid >> 5] = sq; }
    __syncthreads();
    float ts = 0.f, tq = 0.f;
    #pragma unroll
    for (int i = 0; i < 8; ++i) { ts += rs[i]; tq += rq[i]; }
    float mean = ts * (1.0f / EE);
    float var  = tq * (1.0f / EE) - mean * mean;
    float inv  = rsqrtf(var + 1e-5f);
    float4 gv = reinterpret_cast<const float4*>(g)[tid];
    float4 bv = reinterpret_cast<const float4*>(b)[tid];
    float4 o;
    o.x = (v.x - mean) * inv * gv.x + bv.x;
    o.y = (v.y - mean) * inv * gv.y + bv.y;
    o.z = (v.z - mean) * inv * gv.z + bv.z;
    o.w = (v.w - mean) * inv * gv.w + bv.w;
    py[tid] = o;
}

// ---------------- softmax over rows of length 1024 --------------------------
__global__ void softmax_k(float* __restrict__ s) {
    float4* p = reinterpret_cast<float4*>(s) + (long long)blockIdx.x * 256 + threadIdx.x;
    int tid = threadIdx.x;
    float4 v = *p;
    __shared__ float red[8];
    float m = fmaxf(fmaxf(v.x, v.y), fmaxf(v.z, v.w));
    #pragma unroll
    for (int o = 16; o; o >>= 1) m = fmaxf(m, __shfl_xor_sync(~0u, m, o));
    if ((tid & 31) == 0) red[tid >> 5] = m;
    __syncthreads();
    float mm = red[0];
    #pragma unroll
    for (int i = 1; i < 8; ++i) mm = fmaxf(mm, red[i]);
    v.x = __expf(v.x - mm); v.y = __expf(v.y - mm);
    v.z = __expf(v.z - mm); v.w = __expf(v.w - mm);
    float ss = v.x + v.y + v.z + v.w;
    #pragma unroll
    for (int o = 16; o; o >>= 1) ss += __shfl_xor_sync(~0u, ss, o);
    __syncthreads();
    if ((tid & 31) == 0) red[tid >> 5] = ss;
    __syncthreads();
    float tot = red[0];
    #pragma unroll
    for (int i = 1; i < 8; ++i) tot += red[i];
    float inv = 1.0f / tot;
    v.x *= inv; v.y *= inv; v.z *= inv; v.w *= inv;
    *p = v;
}

// ---------------- generic tiled SGEMM ---------------------------------------
// C = act( alpha * A@B (+bias) (+Res) )
// Batched via blockIdx.z with (z/Hdiv, z%Hdiv) strides.
// Requires M%BM==0, N%BN==0, K%BK==0 (true for all shapes here).
template<int BM, int BN, int BK, int TM, int TN, bool TRANSB, int ACT>
__global__ void __launch_bounds__((BM/TM)*(BN/TN))
gemm_k(const float* __restrict__ A, const float* __restrict__ B,
       const float* __restrict__ bias, const float* __restrict__ Res,
       float* __restrict__ C,
       int M, int N, int K, int lda, int ldb, int ldc,
       int Hdiv,
       long long sA0, long long sA1, long long sB0, long long sB1,
       long long sC0, long long sC1,
       float alpha) {
    constexpr int NT = (BM/TM)*(BN/TN);
    int z = blockIdx.z;
    int zb = z / Hdiv, zh = z % Hdiv;
    A += (long long)zb * sA0 + (long long)zh * sA1;
    B += (long long)zb * sB0 + (long long)zh * sB1;
    long long offC = (long long)zb * sC0 + (long long)zh * sC1;
    C += offC;
    if (Res) Res += offC;

    __shared__ float As[BK][BM + 4];
    __shared__ float Bs[BK][BN + 4];

    int tid = threadIdx.x;
    int m0 = blockIdx.y * BM;
    int n0 = blockIdx.x * BN;
    constexpr int TX = BN / TN;
    int tx = tid % TX;
    int ty = tid / TX;

    float acc[TM][TN];
    #pragma unroll
    for (int i = 0; i < TM; ++i)
        #pragma unroll
        for (int j = 0; j < TN; ++j) acc[i][j] = 0.f;

    constexpr int A_IT = (BM * BK) / (4 * NT);
    constexpr int B_IT = (BK * BN) / (4 * NT);

    for (int k0 = 0; k0 < K; k0 += BK) {
        #pragma unroll
        for (int it = 0; it < A_IT; ++it) {
            int idx = tid + it * NT;
            int row = idx / (BK / 4);
            int c4  = idx % (BK / 4);
            float4 a = *reinterpret_cast<const float4*>(
                &A[(long long)(m0 + row) * lda + k0 + c4 * 4]);
            As[c4*4+0][row] = a.x; As[c4*4+1][row] = a.y;
            As[c4*4+2][row] = a.z; As[c4*4+3][row] = a.w;
        }
        if (!TRANSB) {
            #pragma unroll
            for (int it = 0; it < B_IT; ++it) {
                int idx = tid + it * NT;
                int row = idx / (BN / 4);
                int c4  = idx % (BN / 4);
                float4 b = *reinterpret_cast<const float4*>(
                    &B[(long long)(k0 + row) * ldb + n0 + c4 * 4]);
                *reinterpret_cast<float4*>(&Bs[row][c4 * 4]) = b;
            }
        } else {
            // B physical [N,K]; Bs[k][n] = B[n,k]
            #pragma unroll
            for (int it = 0; it < B_IT; ++it) {
                int idx = tid + it * NT;
                int row = idx / (BK / 4);
                int c4  = idx % (BK / 4);
                float4 b = *reinterpret_cast<const float4*>(
                    &B[(long long)(n0 + row) * ldb + k0 + c4 * 4]);
                Bs[c4*4+0][row] = b.x; Bs[c4*4+1][row] = b.y;
                Bs[c4*4+2][row] = b.z; Bs[c4*4+3][row] = b.w;
            }
        }
        __syncthreads();
        #pragma unroll
        for (int k = 0; k < BK; ++k) {
            float af[TM], bf[TN];
            #pragma unroll
            for (int i = 0; i < TM; ++i) af[i] = As[k][ty * TM + i];
            #pragma unroll
            for (int j = 0; j < TN; ++j) bf[j] = Bs[k][tx * TN + j];
            #pragma unroll
            for (int i = 0; i < TM; ++i)
                #pragma unroll
                for (int j = 0; j < TN; ++j)
                    acc[i][j] = fmaf(af[i], bf[j], acc[i][j]);
        }
        __syncthreads();
    }

    #pragma unroll
    for (int i = 0; i < TM; ++i) {
        long long row = m0 + ty * TM + i;
        #pragma unroll
        for (int j = 0; j < TN; ++j) {
            int col = n0 + tx * TN + j;
            float v = acc[i][j] * alpha;
            if (bias) v += bias[col];
            if (Res)  v += Res[row * ldc + col];
            if (ACT == 1) v = 0.5f * v * (1.0f + erff(v * 0.70710678118654752f));
            C[row * ldc + col] = v;
        }
    }
}

// ---------------- launcher ---------------------------------------------------
extern "C" void kernel_launch(void* const* d_in, const int* in_sizes, int n_in,
                              void* d_out, int out_size) {
    const float* x     = (const float*)d_in[0];
    const float* Wq    = (const float*)d_in[1];
    const float* bq    = (const float*)d_in[2];
    const float* Wk    = (const float*)d_in[3];
    const float* bk    = (const float*)d_in[4];
    const float* Wv    = (const float*)d_in[5];
    const float* bv    = (const float*)d_in[6];
    const float* Wo    = (const float*)d_in[7];
    const float* bo    = (const float*)d_in[8];
    const float* g1    = (const float*)d_in[9];
    const float* beta1 = (const float*)d_in[10];
    const float* g2    = (const float*)d_in[11];
    const float* beta2 = (const float*)d_in[12];
    const float* W1    = (const float*)d_in[13];
    const float* c1    = (const float*)d_in[14];
    const float* W2    = (const float*)d_in[15];
    const float* c2    = (const float*)d_in[16];
    float* out = (float*)d_out;

    float *xn, *qkv, *sc, *ctx, *x1, *hb, *Wqkv, *bqkv;
    cudaGetSymbolAddress((void**)&xn,   g_xn);
    cudaGetSymbolAddress((void**)&qkv,  g_qkv);
    cudaGetSymbolAddress((void**)&sc,   g_sc);
    cudaGetSymbolAddress((void**)&ctx,  g_ctx);
    cudaGetSymbolAddress((void**)&x1,   g_x1);
    cudaGetSymbolAddress((void**)&hb,   g_h);
    cudaGetSymbolAddress((void**)&Wqkv, g_Wqkv);
    cudaGetSymbolAddress((void**)&bqkv, g_bqkv);

    // 1) repack QKV weights into one [E, 3E] matrix
    repack_k<<<(HH * EE * DD + 255) / 256, 256>>>(Wq, Wk, Wv, bq, bk, bv, Wqkv, bqkv);

    // 2) LN1
    layernorm_k<<<MM, 256>>>(x, g1, beta1, xn);

    // 3) fused QKV projection: [8192,1024] x [1024,3072]
    gemm_k<128,128,16,8,8,false,0><<<dim3(3*EE/128, MM/128, 1), 256>>>(
        xn, Wqkv, bqkv, nullptr, qkv,
        MM, 3*EE, EE, EE, 3*EE, 3*EE,
        1, 0,0,0,0,0,0, 1.0f);

    // 4) scores = 0.125 * Q K^T, batched over (b,h)
    gemm_k<128,128,16,8,8,true,0><<<dim3(SS/128, SS/128, BB*HH), 256>>>(
        qkv, qkv + EE, nullptr, nullptr, sc,
        SS, SS, DD, 3*EE, 3*EE, SS,
        HH,
        (long long)SS * 3*EE, DD,          // A(q): per-b, per-h
        (long long)SS * 3*EE, DD,          // B(k)
        (long long)HH * SS * SS, (long long)SS * SS,
        0.125f);

    // 5) softmax
    softmax_k<<<BB * HH * SS, 256>>>(sc);

    // 6) ctx = P @ V, written directly into [B,S,H,D] = [M,E]
    gemm_k<128,64,16,8,4,false,0><<<dim3(1, SS/128, BB*HH), 256>>>(
        sc, qkv + 2*EE, nullptr, nullptr, ctx,
        SS, DD, SS, SS, 3*EE, EE,
        HH,
        (long long)HH * SS * SS, (long long)SS * SS,
        (long long)SS * 3*EE, DD,
        (long long)SS * EE, DD,
        1.0f);

    // 7) out-proj + bias + residual: x1 = x + ctx @ Wo + bo
    gemm_k<128,128,16,8,8,false,0><<<dim3(EE/128, MM/128, 1), 256>>>(
        ctx, Wo, bo, x, x1,
        MM, EE, EE, EE, EE, EE,
        1, 0,0,0,0,0,0, 1.0f);

    // 8) LN2
    layernorm_k<<<MM, 256>>>(x1, g2, beta2, xn);

    // 9) MLP up + exact GELU
    gemm_k<128,128,16,8,8,false,1><<<dim3(FFF/128, MM/128, 1), 256>>>(
        xn, W1, c1, nullptr, hb,
        MM, FFF, EE, EE, FFF, FFF,
        1, 0,0,0,0,0,0, 1.0f);

    // 10) MLP down + bias + residual -> d_out
    gemm_k<128,128,16,8,8,false,0><<<dim3(EE/128, MM/128, 1), 256>>>(
        hb, W2, c2, x1, out,
        MM, EE, FFF, FFF, EE, EE,
        1, 0,0,0,0,0,0, 1.0f);
}

// round 2
// speedup vs baseline: 2.9489x; 2.9489x over previous
#include <cuda_runtime.h>
#include <cuda_bf16.h>
#include <math.h>
#include <stdint.h>

// Problem constants
#define BB  8
#define SS  1024
#define EE  1024
#define HH  16
#define DD  64
#define FFF 4096
#define MM  (BB*SS)          // 8192 rows

// ---------------- scratch (static device globals; no cudaMalloc allowed) ----
__device__ float g_xn  [(long long)MM*EE];        // 32 MB
__device__ float g_qkv [(long long)MM*3*EE];      // 96 MB
__device__ float g_sc  [(long long)BB*HH*SS*SS];  // 512 MB
__device__ float g_ctx [(long long)MM*EE];        // 32 MB
__device__ float g_x1  [(long long)MM*EE];        // 32 MB
__device__ float g_h   [(long long)MM*FFF];       // 128 MB
__device__ float g_Wqkv[(long long)EE*3*EE];      // 12 MB
__device__ float g_bqkv[3*EE];

// ---------------- weight repack: Wq/Wk/Wv [H,E,D] -> Wqkv [E, 3E] ----------
__global__ void repack_k(const float* __restrict__ Wq, const float* __restrict__ Wk,
                         const float* __restrict__ Wv,
                         const float* __restrict__ bq, const float* __restrict__ bk,
                         const float* __restrict__ bv,
                         float* __restrict__ Wqkv, float* __restrict__ bqkv) {
    int idx = blockIdx.x * blockDim.x + threadIdx.x;
    const int total = HH * EE * DD;
    if (idx < total) {
        int h = idx / (EE * DD);
        int e = (idx / DD) % EE;
        int d = idx % DD;
        int col = h * DD + d;
        long long base = (long long)e * (3 * EE);
        Wqkv[base + col]          = Wq[idx];
        Wqkv[base + EE + col]     = Wk[idx];
        Wqkv[base + 2 * EE + col] = Wv[idx];
    }
    if (idx < EE) {
        bqkv[idx]          = bq[idx];
        bqkv[EE + idx]     = bk[idx];
        bqkv[2 * EE + idx] = bv[idx];
    }
}

// ---------------- layernorm: one block per row of 1024 ---------------------
__global__ void layernorm_k(const float* __restrict__ x, const float* __restrict__ g,
                            const float* __restrict__ b, float* __restrict__ y) {
    const float4* px = reinterpret_cast<const float4*>(x) + (long long)blockIdx.x * 256;
    float4*       py = reinterpret_cast<float4*>(y)       + (long long)blockIdx.x * 256;
    int tid = threadIdx.x;
    float4 v = px[tid];
    float s  = v.x + v.y + v.z + v.w;
    float sq = v.x*v.x + v.y*v.y + v.z*v.z + v.w*v.w;
    __shared__ float rs[8], rq[8];
    #pragma unroll
    for (int o = 16; o; o >>= 1) {
        s  += __shfl_xor_sync(~0u, s,  o);
        sq += __shfl_xor_sync(~0u, sq, o);
    }
    if ((tid & 31) == 0) { rs[tid >> 5] = s; rq[tid >> 5] = sq; }
    __syncthreads();
    float ts = 0.f, tq = 0.f;
    #pragma unroll
    for (int i = 0; i < 8; ++i) { ts += rs[i]; tq += rq[i]; }
    float mean = ts * (1.0f / EE);
    float var  = tq * (1.0f / EE) - mean * mean;
    float inv  = rsqrtf(var + 1e-5f);
    float4 gv = reinterpret_cast<const float4*>(g)[tid];
    float4 bv = reinterpret_cast<const float4*>(b)[tid];
    float4 o;
    o.x = (v.x - mean) * inv * gv.x + bv.x;
    o.y = (v.y - mean) * inv * gv.y + bv.y;
    o.z = (v.z - mean) * inv * gv.z + bv.z;
    o.w = (v.w - mean) * inv * gv.w + bv.w;
    py[tid] = o;
}

// ---------------- softmax over rows of length 1024 --------------------------
__global__ void softmax_k(float* __restrict__ s) {
    float4* p = reinterpret_cast<float4*>(s) + (long long)blockIdx.x * 256 + threadIdx.x;
    int tid = threadIdx.x;
    float4 v = *p;
    __shared__ float red[8];
    float m = fmaxf(fmaxf(v.x, v.y), fmaxf(v.z, v.w));
    #pragma unroll
    for (int o = 16; o; o >>= 1) m = fmaxf(m, __shfl_xor_sync(~0u, m, o));
    if ((tid & 31) == 0) red[tid >> 5] = m;
    __syncthreads();
    float mm = red[0];
    #pragma unroll
    for (int i = 1; i < 8; ++i) mm = fmaxf(mm, red[i]);
    v.x = __expf(v.x - mm); v.y = __expf(v.y - mm);
    v.z = __expf(v.z - mm); v.w = __expf(v.w - mm);
    float ss = v.x + v.y + v.z + v.w;
    #pragma unroll
    for (int o = 16; o; o >>= 1) ss += __shfl_xor_sync(~0u, ss, o);
    __syncthreads();
    if ((tid & 31) == 0) red[tid >> 5] = ss;
    __syncthreads();
    float tot = red[0];
    #pragma unroll
    for (int i = 1; i < 8; ++i) tot += red[i];
    float inv = 1.0f / tot;
    v.x *= inv; v.y *= inv; v.z *= inv; v.w *= inv;
    *p = v;
}

// ---------------- tf32 tensor-core GEMM --------------------------------------
__device__ __forceinline__ uint32_t f2tf32(float x) {
    uint32_t u; asm("cvt.rna.tf32.f32 %0, %1;" : "=r"(u) : "f"(x)); return u;
}
__device__ __forceinline__ uint32_t smem_u32(const void* p) {
    uint32_t a;
    asm("{ .reg .u64 t; cvta.to.shared.u64 t, %1; cvt.u32.u64 %0, t; }" : "=r"(a) : "l"(p));
    return a;
}
__device__ __forceinline__ void cp16(uint32_t dst, const void* src) {
    asm volatile("cp.async.cg.shared.global [%0], [%1], 16;" :: "r"(dst), "l"(src));
}
__device__ __forceinline__ void mma_tf32(float* d, const uint32_t* a, const uint32_t* b) {
    asm volatile(
        "mma.sync.aligned.m16n8k8.row.col.f32.tf32.tf32.f32 "
        "{%0,%1,%2,%3}, {%4,%5,%6,%7}, {%8,%9}, {%0,%1,%2,%3};"
        : "+f"(d[0]), "+f"(d[1]), "+f"(d[2]), "+f"(d[3])
        : "r"(a[0]), "r"(a[1]), "r"(a[2]), "r"(a[3]), "r"(b[0]), "r"(b[1]));
}

// C = act( alpha * A@B (+bias) (+Res) ), batched over blockIdx.z.
// BM x BN block tile, BK=32, 256 threads (8 warps as 4(m) x 2(n)).
template<int BM, int BN, bool TRANSB, int ACT>
__global__ void __launch_bounds__(256)
mma_gemm(const float* __restrict__ A, const float* __restrict__ B,
         const float* __restrict__ bias, const float* __restrict__ Res,
         float* __restrict__ C,
         int K, int lda, int ldb, int ldc, int Hdiv,
         long long sA0, long long sA1, long long sB0, long long sB1,
         long long sC0, long long sC1, float alpha) {
    constexpr int BK   = 32;
    constexpr int ASTR = BK + 4;                     // 36 : 4r+q conflict-free
    constexpr int ASZ  = BM * ASTR;
    constexpr int BROW = TRANSB ? BN : BK;
    constexpr int BSTR = TRANSB ? (BK + 4) : (BN + 8);  // trans: 36, non: ≡8 mod 32
    constexpr int BSZ  = BROW * BSTR;
    constexpr int WM   = BM / 4;
    constexpr int WN   = BN / 2;
    constexpr int MT   = WM / 16;
    constexpr int NT   = WN / 8;
    constexpr int A_CH = BK / 4;                     // 16B chunks per A row
    constexpr int B_CH = (TRANSB ? BK : BN) / 4;
    constexpr int A_IT = (BM * A_CH) / 256;
    constexpr int B_IT = (BROW * B_CH) / 256;

    extern __shared__ float sm[];
    const uint32_t s_base = smem_u32(sm);

    int z  = blockIdx.z;
    int zb = z / Hdiv, zh = z % Hdiv;
    A += (long long)zb * sA0 + (long long)zh * sA1;
    B += (long long)zb * sB0 + (long long)zh * sB1;
    long long offC = (long long)zb * sC0 + (long long)zh * sC1;
    C += offC;
    if (Res) Res += offC;

    int tid  = threadIdx.x;
    int lane = tid & 31;
    int warp = tid >> 5;
    int wm   = (warp & 3) * WM;
    int wn   = (warp >> 2) * WN;
    int m0   = blockIdx.y * BM;
    int n0   = blockIdx.x * BN;
    int r    = lane >> 2;
    int q    = lane & 3;

    float acc[MT][NT][4];
    #pragma unroll
    for (int i = 0; i < MT; ++i)
        #pragma unroll
        for (int j = 0; j < NT; ++j)
            #pragma unroll
            for (int t = 0; t < 4; ++t) acc[i][j][t] = 0.f;

    auto load_tiles = [&](int k0, int buf) {
        #pragma unroll
        for (int it = 0; it < A_IT; ++it) {
            int idx = tid + it * 256;
            int row = idx / A_CH, ch = idx % A_CH;
            cp16(s_base + (uint32_t)((buf * ASZ + row * ASTR + ch * 4) * 4),
                 A + (long long)(m0 + row) * lda + k0 + ch * 4);
        }
        #pragma unroll
        for (int it = 0; it < B_IT; ++it) {
            int idx = tid + it * 256;
            int row = idx / B_CH, ch = idx % B_CH;
            const float* src = TRANSB
                ? (B + (long long)(n0 + row) * ldb + k0 + ch * 4)
                : (B + (long long)(k0 + row) * ldb + n0 + ch * 4);
            cp16(s_base + (uint32_t)((2 * ASZ + buf * BSZ + row * BSTR + ch * 4) * 4), src);
        }
    };

    load_tiles(0, 0);
    asm volatile("cp.async.commit_group;");

    int buf = 0;
    for (int k0 = 0; k0 < K; k0 += BK) {
        asm volatile("cp.async.wait_group 0;");
        __syncthreads();
        if (k0 + BK < K) {
            load_tiles(k0 + BK, buf ^ 1);
            asm volatile("cp.async.commit_group;");
        }
        const float* as = sm + buf * ASZ;
        const float* bs = sm + 2 * ASZ + buf * BSZ;
        #pragma unroll
        for (int kk = 0; kk < BK / 8; ++kk) {
            uint32_t af[MT][4];
            #pragma unroll
            for (int mt = 0; mt < MT; ++mt) {
                const float* p = as + (wm + mt * 16 + r) * ASTR + kk * 8 + q;
                af[mt][0] = f2tf32(p[0]);
                af[mt][1] = f2tf32(p[8 * ASTR]);
                af[mt][2] = f2tf32(p[4]);
                af[mt][3] = f2tf32(p[8 * ASTR + 4]);
            }
            uint32_t bfr[NT][2];
            #pragma unroll
            for (int nt = 0; nt < NT; ++nt) {
                if (TRANSB) {
                    const float* p = bs + (wn + nt * 8 + r) * BSTR + kk * 8 + q;
                    bfr[nt][0] = f2tf32(p[0]);
                    bfr[nt][1] = f2tf32(p[4]);
                } else {
                    const float* p = bs + (kk * 8 + q) * BSTR + wn + nt * 8 + r;
                    bfr[nt][0] = f2tf32(p[0]);
                    bfr[nt][1] = f2tf32(p[4 * BSTR]);
                }
            }
            #pragma unroll
            for (int mt = 0; mt < MT; ++mt)
                #pragma unroll
                for (int nt = 0; nt < NT; ++nt)
                    mma_tf32(acc[mt][nt], af[mt], bfr[nt]);
        }
        buf ^= 1;
    }

    // epilogue: c0,c1 at (row, col..col+1); c2,c3 at (row+8, col..col+1)
    #pragma unroll
    for (int mt = 0; mt < MT; ++mt) {
        #pragma unroll
        for (int nt = 0; nt < NT; ++nt) {
            long long row = m0 + wm + mt * 16 + r;
            int col = n0 + wn + nt * 8 + 2 * q;
            float2 v0 = make_float2(acc[mt][nt][0] * alpha, acc[mt][nt][1] * alpha);
            float2 v1 = make_float2(acc[mt][nt][2] * alpha, acc[mt][nt][3] * alpha);
            if (bias) {
                float2 bb = *reinterpret_cast<const float2*>(&bias[col]);
                v0.x += bb.x; v0.y += bb.y; v1.x += bb.x; v1.y += bb.y;
            }
            if (Res) {
                float2 r0 = *reinterpret_cast<const float2*>(&Res[row * ldc + col]);
                float2 r1 = *reinterpret_cast<const float2*>(&Res[(row + 8) * ldc + col]);
                v0.x += r0.x; v0.y += r0.y; v1.x += r1.x; v1.y += r1.y;
            }
            if (ACT == 1) {
                v0.x = 0.5f * v0.x * (1.0f + erff(v0.x * 0.70710678118654752f));
                v0.y = 0.5f * v0.y * (1.0f + erff(v0.y * 0.70710678118654752f));
                v1.x = 0.5f * v1.x * (1.0f + erff(v1.x * 0.70710678118654752f));
                v1.y = 0.5f * v1.y * (1.0f + erff(v1.y * 0.70710678118654752f));
            }
            *reinterpret_cast<float2*>(&C[row * ldc + col])       = v0;
            *reinterpret_cast<float2*>(&C[(row + 8) * ldc + col]) = v1;
        }
    }
}

// ---------------- launcher ---------------------------------------------------
extern "C" void kernel_launch(void* const* d_in, const int* in_sizes, int n_in,
                              void* d_out, int out_size) {
    const float* x     = (const float*)d_in[0];
    const float* Wq    = (const float*)d_in[1];
    const float* bq    = (const float*)d_in[2];
    const float* Wk    = (const float*)d_in[3];
    const float* bk    = (const float*)d_in[4];
    const float* Wv    = (const float*)d_in[5];
    const float* bv    = (const float*)d_in[6];
    const float* Wo    = (const float*)d_in[7];
    const float* bo    = (const float*)d_in[8];
    const float* g1    = (const float*)d_in[9];
    const float* beta1 = (const float*)d_in[10];
    const float* g2    = (const float*)d_in[11];
    const float* beta2 = (const float*)d_in[12];
    const float* W1    = (const float*)d_in[13];
    const float* c1    = (const float*)d_in[14];
    const float* W2    = (const float*)d_in[15];
    const float* c2    = (const float*)d_in[16];
    float* out = (float*)d_out;

    float *xn, *qkv, *sc, *ctx, *x1, *hb, *Wqkv, *bqkv;
    cudaGetSymbolAddress((void**)&xn,   g_xn);
    cudaGetSymbolAddress((void**)&qkv,  g_qkv);
    cudaGetSymbolAddress((void**)&sc,   g_sc);
    cudaGetSymbolAddress((void**)&ctx,  g_ctx);
    cudaGetSymbolAddress((void**)&x1,   g_x1);
    cudaGetSymbolAddress((void**)&hb,   g_h);
    cudaGetSymbolAddress((void**)&Wqkv, g_Wqkv);
    cudaGetSymbolAddress((void**)&bqkv, g_bqkv);

    // dynamic smem sizes (bytes) per instantiation
    const int SM_NT128 = (2 * 128 * 36 + 2 * 32 * 136) * 4;   // 71680
    const int SM_T128  = (2 * 128 * 36 + 2 * 128 * 36) * 4;   // 73728
    const int SM_NT64  = (2 * 128 * 36 + 2 * 32 * 72) * 4;    // 55296

    static bool attr_done = false;
    if (!attr_done) {
        cudaFuncSetAttribute((const void*)mma_gemm<128,128,false,0>,
                             cudaFuncAttributeMaxDynamicSharedMemorySize, SM_NT128);
        cudaFuncSetAttribute((const void*)mma_gemm<128,128,false,1>,
                             cudaFuncAttributeMaxDynamicSharedMemorySize, SM_NT128);
        cudaFuncSetAttribute((const void*)mma_gemm<128,128,true,0>,
                             cudaFuncAttributeMaxDynamicSharedMemorySize, SM_T128);
        cudaFuncSetAttribute((const void*)mma_gemm<128,64,false,0>,
                             cudaFuncAttributeMaxDynamicSharedMemorySize, SM_NT64);
        attr_done = true;
    }

    // 1) repack QKV weights
    repack_k<<<(HH * EE * DD + 255) / 256, 256>>>(Wq, Wk, Wv, bq, bk, bv, Wqkv, bqkv);

    // 2) LN1
    layernorm_k<<<MM, 256>>>(x, g1, beta1, xn);

    // 3) fused QKV projection: [8192,1024] x [1024,3072]
    mma_gemm<128,128,false,0><<<dim3(3*EE/128, MM/128, 1), 256, SM_NT128>>>(
        xn, Wqkv, bqkv, nullptr, qkv,
        EE, EE, 3*EE, 3*EE,
        1, 0,0,0,0,0,0, 1.0f);

    // 4) scores = 0.125 * Q K^T, batched over (b,h)
    mma_gemm<128,128,true,0><<<dim3(SS/128, SS/128, BB*HH), 256, SM_T128>>>(
        qkv, qkv + EE, nullptr, nullptr, sc,
        DD, 3*EE, 3*EE, SS,
        HH,
        (long long)SS * 3*EE, DD,
        (long long)SS * 3*EE, DD,
        (long long)HH * SS * SS, (long long)SS * SS,
        0.125f);

    // 5) softmax
    softmax_k<<<BB * HH * SS, 256>>>(sc);

    // 6) ctx = P @ V, written directly into [B,S,H,D] = [M,E]
    mma_gemm<128,64,false,0><<<dim3(1, SS/128, BB*HH), 256, SM_NT64>>>(
        sc, qkv + 2*EE, nullptr, nullptr, ctx,
        SS, SS, 3*EE, EE,
        HH,
        (long long)HH * SS * SS, (long long)SS * SS,
        (long long)SS * 3*EE, DD,
        (long long)SS * EE, DD,
        1.0f);

    // 7) out-proj + bias + residual: x1 = x + ctx @ Wo + bo
    mma_gemm<128,128,false,0><<<dim3(EE/128, MM/128, 1), 256, SM_NT128>>>(
        ctx, Wo, bo, x, x1,
        EE, EE, EE, EE,
        1, 0,0,0,0,0,0, 1.0f);

    // 8) LN2
    layernorm_k<<<MM, 256>>>(x1, g2, beta2, xn);

    // 9) MLP up + exact GELU
    mma_gemm<128,128,false,1><<<dim3(FFF/128, MM/128, 1), 256, SM_NT128>>>(
        xn, W1, c1, nullptr, hb,
        EE, EE, FFF, FFF,
        1, 0,0,0,0,0,0, 1.0f);

    // 10) MLP down + bias + residual -> d_out
    mma_gemm<128,128,false,0><<<dim3(EE/128, MM/128, 1), 256, SM_NT128>>>(
        hb, W2, c2, x1, out,
        FFF, FFF, EE, EE,
        1, 0,0,0,0,0,0, 1.0f);
}

// round 3
// speedup vs baseline: 3.3032x; 1.1201x over previous
#include <cuda_runtime.h>
#include <cuda_bf16.h>
#include <math.h>
#include <stdint.h>

// Problem constants
#define BB  8
#define SS  1024
#define EE  1024
#define HH  16
#define DD  64
#define FFF 4096
#define MM  (BB*SS)          // 8192 rows

// ---------------- scratch (static device globals; no cudaMalloc allowed) ----
__device__ float g_xn  [(long long)MM*EE];        // 32 MB  (tf32-rounded)
__device__ float g_qkv [(long long)MM*3*EE];      // 96 MB  (tf32-rounded)
__device__ float g_sc  [(long long)BB*HH*SS*SS];  // 512 MB
__device__ float g_ctx [(long long)MM*EE];        // 32 MB  (tf32-rounded)
__device__ float g_x1  [(long long)MM*EE];        // 32 MB  (f32)
__device__ float g_h   [(long long)MM*FFF];       // 128 MB (tf32-rounded)
__device__ float g_Wqkv[(long long)EE*3*EE];      // 12 MB  (tf32-rounded)
__device__ float g_bqkv[3*EE];
__device__ float g_Wo  [(long long)EE*EE];        // 4 MB   (tf32-rounded)
__device__ float g_W1  [(long long)EE*FFF];       // 16 MB  (tf32-rounded)
__device__ float g_W2  [(long long)FFF*EE];       // 16 MB  (tf32-rounded)

__device__ __forceinline__ float rnd_tf32(float x) {
    uint32_t u; asm("cvt.rna.tf32.f32 %0, %1;" : "=r"(u) : "f"(x));
    return __uint_as_float(u);
}

// ---------------- weight repack: Wq/Wk/Wv [H,E,D] -> Wqkv [E, 3E] (tf32) ----
__global__ void repack_k(const float* __restrict__ Wq, const float* __restrict__ Wk,
                         const float* __restrict__ Wv,
                         const float* __restrict__ bq, const float* __restrict__ bk,
                         const float* __restrict__ bv,
                         float* __restrict__ Wqkv, float* __restrict__ bqkv) {
    int idx = blockIdx.x * blockDim.x + threadIdx.x;
    const int total = HH * EE * DD;
    if (idx < total) {
        int h = idx / (EE * DD);
        int e = (idx / DD) % EE;
        int d = idx % DD;
        int col = h * DD + d;
        long long base = (long long)e * (3 * EE);
        Wqkv[base + col]          = rnd_tf32(Wq[idx]);
        Wqkv[base + EE + col]     = rnd_tf32(Wk[idx]);
        Wqkv[base + 2 * EE + col] = rnd_tf32(Wv[idx]);
    }
    if (idx < EE) {
        bqkv[idx]          = bq[idx];
        bqkv[EE + idx]     = bk[idx];
        bqkv[2 * EE + idx] = bv[idx];
    }
}

// ---------------- tf32-round a weight matrix into scratch -------------------
__global__ void cvtw_k(const float* __restrict__ src, float* __restrict__ dst, int n4) {
    int i = blockIdx.x * blockDim.x + threadIdx.x;
    if (i < n4) {
        float4 v = reinterpret_cast<const float4*>(src)[i];
        v.x = rnd_tf32(v.x); v.y = rnd_tf32(v.y);
        v.z = rnd_tf32(v.z); v.w = rnd_tf32(v.w);
        reinterpret_cast<float4*>(dst)[i] = v;
    }
}

// ---------------- layernorm: one block per row of 1024 (tf32-rounded out) ---
__global__ void layernorm_k(const float* __restrict__ x, const float* __restrict__ g,
                            const float* __restrict__ b, float* __restrict__ y) {
    const float4* px = reinterpret_cast<const float4*>(x) + (long long)blockIdx.x * 256;
    float4*       py = reinterpret_cast<float4*>(y)       + (long long)blockIdx.x * 256;
    int tid = threadIdx.x;
    float4 v = px[tid];
    float s  = v.x + v.y + v.z + v.w;
    float sq = v.x*v.x + v.y*v.y + v.z*v.z + v.w*v.w;
    __shared__ float rs[8], rq[8];
    #pragma unroll
    for (int o = 16; o; o >>= 1) {
        s  += __shfl_xor_sync(~0u, s,  o);
        sq += __shfl_xor_sync(~0u, sq, o);
    }
    if ((tid & 31) == 0) { rs[tid >> 5] = s; rq[tid >> 5] = sq; }
    __syncthreads();
    float ts = 0.f, tq = 0.f;
    #pragma unroll
    for (int i = 0; i < 8; ++i) { ts += rs[i]; tq += rq[i]; }
    float mean = ts * (1.0f / EE);
    float var  = tq * (1.0f / EE) - mean * mean;
    float inv  = rsqrtf(var + 1e-5f);
    float4 gv = reinterpret_cast<const float4*>(g)[tid];
    float4 bv = reinterpret_cast<const float4*>(b)[tid];
    float4 o;
    o.x = rnd_tf32((v.x - mean) * inv * gv.x + bv.x);
    o.y = rnd_tf32((v.y - mean) * inv * gv.y + bv.y);
    o.z = rnd_tf32((v.z - mean) * inv * gv.z + bv.z);
    o.w = rnd_tf32((v.w - mean) * inv * gv.w + bv.w);
    py[tid] = o;
}

// ---------------- softmax over rows of length 1024 (tf32-rounded out) -------
__global__ void softmax_k(float* __restrict__ s) {
    float4* p = reinterpret_cast<float4*>(s) + (long long)blockIdx.x * 256 + threadIdx.x;
    int tid = threadIdx.x;
    float4 v = *p;
    __shared__ float red[8];
    float m = fmaxf(fmaxf(v.x, v.y), fmaxf(v.z, v.w));
    #pragma unroll
    for (int o = 16; o; o >>= 1) m = fmaxf(m, __shfl_xor_sync(~0u, m, o));
    if ((tid & 31) == 0) red[tid >> 5] = m;
    __syncthreads();
    float mm = red[0];
    #pragma unroll
    for (int i = 1; i < 8; ++i) mm = fmaxf(mm, red[i]);
    v.x = __expf(v.x - mm); v.y = __expf(v.y - mm);
    v.z = __expf(v.z - mm); v.w = __expf(v.w - mm);
    float ss = v.x + v.y + v.z + v.w;
    #pragma unroll
    for (int o = 16; o; o >>= 1) ss += __shfl_xor_sync(~0u, ss, o);
    __syncthreads();
    if ((tid & 31) == 0) red[tid >> 5] = ss;
    __syncthreads();
    float tot = red[0];
    #pragma unroll
    for (int i = 1; i < 8; ++i) tot += red[i];
    float inv = 1.0f / tot;
    v.x = rnd_tf32(v.x * inv); v.y = rnd_tf32(v.y * inv);
    v.z = rnd_tf32(v.z * inv); v.w = rnd_tf32(v.w * inv);
    *p = v;
}

// ---------------- tf32 tensor-core GEMM (operands pre-rounded) --------------
__device__ __forceinline__ uint32_t smem_u32(const void* p) {
    uint32_t a;
    asm("{ .reg .u64 t; cvta.to.shared.u64 t, %1; cvt.u32.u64 %0, t; }" : "=r"(a) : "l"(p));
    return a;
}
__device__ __forceinline__ void cp16(uint32_t dst, const void* src) {
    asm volatile("cp.async.cg.shared.global [%0], [%1], 16;" :: "r"(dst), "l"(src));
}
__device__ __forceinline__ void mma_tf32(float* d, const uint32_t* a, const uint32_t* b) {
    asm volatile(
        "mma.sync.aligned.m16n8k8.row.col.f32.tf32.tf32.f32 "
        "{%0,%1,%2,%3}, {%4,%5,%6,%7}, {%8,%9}, {%0,%1,%2,%3};"
        : "+f"(d[0]), "+f"(d[1]), "+f"(d[2]), "+f"(d[3])
        : "r"(a[0]), "r"(a[1]), "r"(a[2]), "r"(a[3]), "r"(b[0]), "r"(b[1]));
}

// C = act( alpha * A@B (+bias) (+Res) ), batched over blockIdx.z.
// BM x BN block tile, BK=32, 256 threads (8 warps as 4(m) x 2(n)).
// ROUND: tf32-round outputs (for values consumed by a later GEMM).
template<int BM, int BN, bool TRANSB, int ACT, int ROUND>
__global__ void __launch_bounds__(256)
mma_gemm(const float* __restrict__ A, const float* __restrict__ B,
         const float* __restrict__ bias, const float* __restrict__ Res,
         float* __restrict__ C,
         int K, int lda, int ldb, int ldc, int Hdiv,
         long long sA0, long long sA1, long long sB0, long long sB1,
         long long sC0, long long sC1, float alpha) {
    constexpr int BK   = 32;
    constexpr int ASTR = BK + 4;                     // 36 : 4r+q conflict-free
    constexpr int ASZ  = BM * ASTR;
    constexpr int BROW = TRANSB ? BN : BK;
    constexpr int BSTR = TRANSB ? (BK + 4) : (BN + 8);
    constexpr int BSZ  = BROW * BSTR;
    constexpr int WM   = BM / 4;
    constexpr int WN   = BN / 2;
    constexpr int MT   = WM / 16;
    constexpr int NT   = WN / 8;
    constexpr int A_CH = BK / 4;
    constexpr int B_CH = (TRANSB ? BK : BN) / 4;
    constexpr int A_IT = (BM * A_CH) / 256;
    constexpr int B_IT = (BROW * B_CH) / 256;

    extern __shared__ float sm[];
    const uint32_t s_base = smem_u32(sm);

    int z  = blockIdx.z;
    int zb = z / Hdiv, zh = z % Hdiv;
    A += (long long)zb * sA0 + (long long)zh * sA1;
    B += (long long)zb * sB0 + (long long)zh * sB1;
    long long offC = (long long)zb * sC0 + (long long)zh * sC1;
    C += offC;
    if (Res) Res += offC;

    int tid  = threadIdx.x;
    int lane = tid & 31;
    int warp = tid >> 5;
    int wm   = (warp & 3) * WM;
    int wn   = (warp >> 2) * WN;
    int m0   = blockIdx.y * BM;
    int n0   = blockIdx.x * BN;
    int r    = lane >> 2;
    int q    = lane & 3;

    float acc[MT][NT][4];
    #pragma unroll
    for (int i = 0; i < MT; ++i)
        #pragma unroll
        for (int j = 0; j < NT; ++j)
            #pragma unroll
            for (int t = 0; t < 4; ++t) acc[i][j][t] = 0.f;

    auto load_tiles = [&](int k0, int buf) {
        #pragma unroll
        for (int it = 0; it < A_IT; ++it) {
            int idx = tid + it * 256;
            int row = idx / A_CH, ch = idx % A_CH;
            cp16(s_base + (uint32_t)((buf * ASZ + row * ASTR + ch * 4) * 4),
                 A + (long long)(m0 + row) * lda + k0 + ch * 4);
        }
        #pragma unroll
        for (int it = 0; it < B_IT; ++it) {
            int idx = tid + it * 256;
            int row = idx / B_CH, ch = idx % B_CH;
            const float* src = TRANSB
                ? (B + (long long)(n0 + row) * ldb + k0 + ch * 4)
                : (B + (long long)(k0 + row) * ldb + n0 + ch * 4);
            cp16(s_base + (uint32_t)((2 * ASZ + buf * BSZ + row * BSTR + ch * 4) * 4), src);
        }
    };

    load_tiles(0, 0);
    asm volatile("cp.async.commit_group;");

    int buf = 0;
    for (int k0 = 0; k0 < K; k0 += BK) {
        asm volatile("cp.async.wait_group 0;");
        __syncthreads();
        if (k0 + BK < K) {
            load_tiles(k0 + BK, buf ^ 1);
            asm volatile("cp.async.commit_group;");
        }
        const uint32_t* as = reinterpret_cast<const uint32_t*>(sm) + buf * ASZ;
        const uint32_t* bs = reinterpret_cast<const uint32_t*>(sm) + 2 * ASZ + buf * BSZ;
        #pragma unroll
        for (int kk = 0; kk < BK / 8; ++kk) {
            uint32_t af[MT][4];
            #pragma unroll
            for (int mt = 0; mt < MT; ++mt) {
                const uint32_t* p = as + (wm + mt * 16 + r) * ASTR + kk * 8 + q;
                af[mt][0] = p[0];
                af[mt][1] = p[8 * ASTR];
                af[mt][2] = p[4];
                af[mt][3] = p[8 * ASTR + 4];
            }
            uint32_t bfr[NT][2];
            #pragma unroll
            for (int nt = 0; nt < NT; ++nt) {
                if (TRANSB) {
                    const uint32_t* p = bs + (wn + nt * 8 + r) * BSTR + kk * 8 + q;
                    bfr[nt][0] = p[0];
                    bfr[nt][1] = p[4];
                } else {
                    const uint32_t* p = bs + (kk * 8 + q) * BSTR + wn + nt * 8 + r;
                    bfr[nt][0] = p[0];
                    bfr[nt][1] = p[4 * BSTR];
                }
            }
            #pragma unroll
            for (int mt = 0; mt < MT; ++mt)
                #pragma unroll
                for (int nt = 0; nt < NT; ++nt)
                    mma_tf32(acc[mt][nt], af[mt], bfr[nt]);
        }
        buf ^= 1;
    }

    #pragma unroll
    for (int mt = 0; mt < MT; ++mt) {
        #pragma unroll
        for (int nt = 0; nt < NT; ++nt) {
            long long row = m0 + wm + mt * 16 + r;
            int col = n0 + wn + nt * 8 + 2 * q;
            float2 v0 = make_float2(acc[mt][nt][0] * alpha, acc[mt][nt][1] * alpha);
            float2 v1 = make_float2(acc[mt][nt][2] * alpha, acc[mt][nt][3] * alpha);
            if (bias) {
                float2 bb = *reinterpret_cast<const float2*>(&bias[col]);
                v0.x += bb.x; v0.y += bb.y; v1.x += bb.x; v1.y += bb.y;
            }
            if (Res) {
                float2 r0 = *reinterpret_cast<const float2*>(&Res[row * ldc + col]);
                float2 r1 = *reinterpret_cast<const float2*>(&Res[(row + 8) * ldc + col]);
                v0.x += r0.x; v0.y += r0.y; v1.x += r1.x; v1.y += r1.y;
            }
            if (ACT == 1) {
                v0.x = 0.5f * v0.x * (1.0f + erff(v0.x * 0.70710678118654752f));
                v0.y = 0.5f * v0.y * (1.0f + erff(v0.y * 0.70710678118654752f));
                v1.x = 0.5f * v1.x * (1.0f + erff(v1.x * 0.70710678118654752f));
                v1.y = 0.5f * v1.y * (1.0f + erff(v1.y * 0.70710678118654752f));
            }
            if (ROUND == 1) {
                v0.x = rnd_tf32(v0.x); v0.y = rnd_tf32(v0.y);
                v1.x = rnd_tf32(v1.x); v1.y = rnd_tf32(v1.y);
            }
            *reinterpret_cast<float2*>(&C[row * ldc + col])       = v0;
            *reinterpret_cast<float2*>(&C[(row + 8) * ldc + col]) = v1;
        }
    }
}

// ---------------- launcher ---------------------------------------------------
extern "C" void kernel_launch(void* const* d_in, const int* in_sizes, int n_in,
                              void* d_out, int out_size) {
    const float* x     = (const float*)d_in[0];
    const float* Wq    = (const float*)d_in[1];
    const float* bq    = (const float*)d_in[2];
    const float* Wk    = (const float*)d_in[3];
    const float* bk    = (const float*)d_in[4];
    const float* Wv    = (const float*)d_in[5];
    const float* bv    = (const float*)d_in[6];
    const float* Wo    = (const float*)d_in[7];
    const float* bo    = (const float*)d_in[8];
    const float* g1    = (const float*)d_in[9];
    const float* beta1 = (const float*)d_in[10];
    const float* g2    = (const float*)d_in[11];
    const float* beta2 = (const float*)d_in[12];
    const float* W1    = (const float*)d_in[13];
    const float* c1    = (const float*)d_in[14];
    const float* W2    = (const float*)d_in[15];
    const float* c2    = (const float*)d_in[16];
    float* out = (float*)d_out;

    float *xn, *qkv, *sc, *ctx, *x1, *hb, *Wqkv, *bqkv, *tWo, *tW1, *tW2;
    cudaGetSymbolAddress((void**)&xn,   g_xn);
    cudaGetSymbolAddress((void**)&qkv,  g_qkv);
    cudaGetSymbolAddress((void**)&sc,   g_sc);
    cudaGetSymbolAddress((void**)&ctx,  g_ctx);
    cudaGetSymbolAddress((void**)&x1,   g_x1);
    cudaGetSymbolAddress((void**)&hb,   g_h);
    cudaGetSymbolAddress((void**)&Wqkv, g_Wqkv);
    cudaGetSymbolAddress((void**)&bqkv, g_bqkv);
    cudaGetSymbolAddress((void**)&tWo,  g_Wo);
    cudaGetSymbolAddress((void**)&tW1,  g_W1);
    cudaGetSymbolAddress((void**)&tW2,  g_W2);

    const int SM_NT128 = (2 * 128 * 36 + 2 * 32 * 136) * 4;   // 71680
    const int SM_T128  = (2 * 128 * 36 + 2 * 128 * 36) * 4;   // 73728
    const int SM_NT64  = (2 * 128 * 36 + 2 * 32 * 72) * 4;    // 55296

    static bool attr_done = false;
    if (!attr_done) {
        cudaFuncSetAttribute((const void*)mma_gemm<128,128,false,0,1>,
                             cudaFuncAttributeMaxDynamicSharedMemorySize, SM_NT128);
        cudaFuncSetAttribute((const void*)mma_gemm<128,128,false,0,0>,
                             cudaFuncAttributeMaxDynamicSharedMemorySize, SM_NT128);
        cudaFuncSetAttribute((const void*)mma_gemm<128,128,false,1,1>,
                             cudaFuncAttributeMaxDynamicSharedMemorySize, SM_NT128);
        cudaFuncSetAttribute((const void*)mma_gemm<128,128,true,0,0>,
                             cudaFuncAttributeMaxDynamicSharedMemorySize, SM_T128);
        cudaFuncSetAttribute((const void*)mma_gemm<128,64,false,0,1>,
                             cudaFuncAttributeMaxDynamicSharedMemorySize, SM_NT64);
        attr_done = true;
    }

    // 0) one-time-per-replay weight conversions (idempotent, cheap)
    repack_k<<<(HH * EE * DD + 255) / 256, 256>>>(Wq, Wk, Wv, bq, bk, bv, Wqkv, bqkv);
    cvtw_k<<<(EE*EE/4 + 255) / 256, 256>>>(Wo, tWo, EE*EE/4);
    cvtw_k<<<(EE*FFF/4 + 255) / 256, 256>>>(W1, tW1, EE*FFF/4);
    cvtw_k<<<(FFF*EE/4 + 255) / 256, 256>>>(W2, tW2, FFF*EE/4);

    // 1) LN1 (tf32-rounded out)
    layernorm_k<<<MM, 256>>>(x, g1, beta1, xn);

    // 2) fused QKV projection: [8192,1024] x [1024,3072], round out
    mma_gemm<128,128,false,0,1><<<dim3(3*EE/128, MM/128, 1), 256, SM_NT128>>>(
        xn, Wqkv, bqkv, nullptr, qkv,
        EE, EE, 3*EE, 3*EE,
        1, 0,0,0,0,0,0, 1.0f);

    // 3) scores = 0.125 * Q K^T, batched over (b,h)
    mma_gemm<128,128,true,0,0><<<dim3(SS/128, SS/128, BB*HH), 256, SM_T128>>>(
        qkv, qkv + EE, nullptr, nullptr, sc,
        DD, 3*EE, 3*EE, SS,
        HH,
        (long long)SS * 3*EE, DD,
        (long long)SS * 3*EE, DD,
        (long long)HH * SS * SS, (long long)SS * SS,
        0.125f);

    // 4) softmax (tf32-rounded out)
    softmax_k<<<BB * HH * SS, 256>>>(sc);

    // 5) ctx = P @ V -> [B,S,H,D] = [M,E], round out
    mma_gemm<128,64,false,0,1><<<dim3(1, SS/128, BB*HH), 256, SM_NT64>>>(
        sc, qkv + 2*EE, nullptr, nullptr, ctx,
        SS, SS, 3*EE, EE,
        HH,
        (long long)HH * SS * SS, (long long)SS * SS,
        (long long)SS * 3*EE, DD,
        (long long)SS * EE, DD,
        1.0f);

    // 6) out-proj + bias + residual: x1 = x + ctx @ Wo + bo (f32 out)
    mma_gemm<128,128,false,0,0><<<dim3(EE/128, MM/128, 1), 256, SM_NT128>>>(
        ctx, tWo, bo, x, x1,
        EE, EE, EE, EE,
        1, 0,0,0,0,0,0, 1.0f);

    // 7) LN2 (tf32-rounded out)
    layernorm_k<<<MM, 256>>>(x1, g2, beta2, xn);

    // 8) MLP up + exact GELU, round out
    mma_gemm<128,128,false,1,1><<<dim3(FFF/128, MM/128, 1), 256, SM_NT128>>>(
        xn, tW1, c1, nullptr, hb,
        EE, EE, FFF, FFF,
        1, 0,0,0,0,0,0, 1.0f);

    // 9) MLP down + bias + residual -> d_out (f32)
    mma_gemm<128,128,false,0,0><<<dim3(EE/128, MM/128, 1), 256, SM_NT128>>>(
        hb, tW2, c2, x1, out,
        FFF, FFF, EE, EE,
        1, 0,0,0,0,0,0, 1.0f);
}

// round 4
// speedup vs baseline: 3.7881x; 1.1468x over previous
#include <cuda_runtime.h>
#include <cuda_bf16.h>
#include <math.h>
#include <stdint.h>

// Problem constants
#define BB  8
#define SS  1024
#define EE  1024
#define HH  16
#define DD  64
#define FFF 4096
#define MM  (BB*SS)          // 8192 rows

// ---------------- scratch (static device globals; no cudaMalloc allowed) ----
__device__ float g_xn  [(long long)MM*EE];        // 32 MB  (tf32-rounded)
__device__ float g_qkv [(long long)MM*3*EE];      // 96 MB  (tf32-rounded)
__device__ float g_ctx [(long long)MM*EE];        // 32 MB  (tf32-rounded)
__device__ float g_x1  [(long long)MM*EE];        // 32 MB  (f32)
__device__ float g_h   [(long long)MM*FFF];       // 128 MB (tf32-rounded)
__device__ float g_Wqkv[(long long)EE*3*EE];      // 12 MB  (tf32-rounded)
__device__ float g_bqkv[3*EE];
__device__ float g_Wo  [(long long)EE*EE];        // 4 MB   (tf32-rounded)
__device__ float g_W1  [(long long)EE*FFF];       // 16 MB  (tf32-rounded)
__device__ float g_W2  [(long long)FFF*EE];       // 16 MB  (tf32-rounded)

__device__ __forceinline__ float rnd_tf32(float x) {
    uint32_t u; asm("cvt.rna.tf32.f32 %0, %1;" : "=r"(u) : "f"(x));
    return __uint_as_float(u);
}
__device__ __forceinline__ uint32_t smem_u32(const void* p) {
    uint32_t a;
    asm("{ .reg .u64 t; cvta.to.shared.u64 t, %1; cvt.u32.u64 %0, t; }" : "=r"(a) : "l"(p));
    return a;
}
__device__ __forceinline__ void cp16(uint32_t dst, const void* src) {
    asm volatile("cp.async.cg.shared.global [%0], [%1], 16;" :: "r"(dst), "l"(src));
}
__device__ __forceinline__ void mma_tf32(float* d, const uint32_t* a, const uint32_t* b) {
    asm volatile(
        "mma.sync.aligned.m16n8k8.row.col.f32.tf32.tf32.f32 "
        "{%0,%1,%2,%3}, {%4,%5,%6,%7}, {%8,%9}, {%0,%1,%2,%3};"
        : "+f"(d[0]), "+f"(d[1]), "+f"(d[2]), "+f"(d[3])
        : "r"(a[0]), "r"(a[1]), "r"(a[2]), "r"(a[3]), "r"(b[0]), "r"(b[1]));
}

// ---------------- weight repack: Wq/Wk/Wv [H,E,D] -> Wqkv [E, 3E] (tf32) ----
__global__ void repack_k(const float* __restrict__ Wq, const float* __restrict__ Wk,
                         const float* __restrict__ Wv,
                         const float* __restrict__ bq, const float* __restrict__ bk,
                         const float* __restrict__ bv,
                         float* __restrict__ Wqkv, float* __restrict__ bqkv) {
    int idx = blockIdx.x * blockDim.x + threadIdx.x;
    const int total = HH * EE * DD;
    if (idx < total) {
        int h = idx / (EE * DD);
        int e = (idx / DD) % EE;
        int d = idx % DD;
        int col = h * DD + d;
        long long base = (long long)e * (3 * EE);
        Wqkv[base + col]          = rnd_tf32(Wq[idx]);
        Wqkv[base + EE + col]     = rnd_tf32(Wk[idx]);
        Wqkv[base + 2 * EE + col] = rnd_tf32(Wv[idx]);
    }
    if (idx < EE) {
        bqkv[idx]          = bq[idx];
        bqkv[EE + idx]     = bk[idx];
        bqkv[2 * EE + idx] = bv[idx];
    }
}

// ---------------- tf32-round a weight matrix into scratch -------------------
__global__ void cvtw_k(const float* __restrict__ src, float* __restrict__ dst, int n4) {
    int i = blockIdx.x * blockDim.x + threadIdx.x;
    if (i < n4) {
        float4 v = reinterpret_cast<const float4*>(src)[i];
        v.x = rnd_tf32(v.x); v.y = rnd_tf32(v.y);
        v.z = rnd_tf32(v.z); v.w = rnd_tf32(v.w);
        reinterpret_cast<float4*>(dst)[i] = v;
    }
}

// ---------------- layernorm: one block per row of 1024 (tf32-rounded out) ---
__global__ void layernorm_k(const float* __restrict__ x, const float* __restrict__ g,
                            const float* __restrict__ b, float* __restrict__ y) {
    const float4* px = reinterpret_cast<const float4*>(x) + (long long)blockIdx.x * 256;
    float4*       py = reinterpret_cast<float4*>(y)       + (long long)blockIdx.x * 256;
    int tid = threadIdx.x;
    float4 v = px[tid];
    float s  = v.x + v.y + v.z + v.w;
    float sq = v.x*v.x + v.y*v.y + v.z*v.z + v.w*v.w;
    __shared__ float rs[8], rq[8];
    #pragma unroll
    for (int o = 16; o; o >>= 1) {
        s  += __shfl_xor_sync(~0u, s,  o);
        sq += __shfl_xor_sync(~0u, sq, o);
    }
    if ((tid & 31) == 0) { rs[tid >> 5] = s; rq[tid >> 5] = sq; }
    __syncthreads();
    float ts = 0.f, tq = 0.f;
    #pragma unroll
    for (int i = 0; i < 8; ++i) { ts += rs[i]; tq += rq[i]; }
    float mean = ts * (1.0f / EE);
    float var  = tq * (1.0f / EE) - mean * mean;
    float inv  = rsqrtf(var + 1e-5f);
    float4 gv = reinterpret_cast<const float4*>(g)[tid];
    float4 bv = reinterpret_cast<const float4*>(b)[tid];
    float4 o;
    o.x = rnd_tf32((v.x - mean) * inv * gv.x + bv.x);
    o.y = rnd_tf32((v.y - mean) * inv * gv.y + bv.y);
    o.z = rnd_tf32((v.z - mean) * inv * gv.z + bv.z);
    o.w = rnd_tf32((v.w - mean) * inv * gv.w + bv.w);
    py[tid] = o;
}

// ---------------- fused flash attention -------------------------------------
// grid (S/128, B*H), 256 threads (8 warps). Each warp owns 16 Q rows.
// Q tile [128,64] in register fragments (scaled by 0.125 exactly).
// K/V streamed in 64-row tiles, cp.async double buffered.
// smem floats: K[2][64][68] @0 (8704), V[2][64][72] @8704 (9216),
//              P[128][68]   @17920 (8704, also Q staging). total 26624 fl.
#define KSTR 68
#define VSTR 72
#define PSTR 68
#define SM_FLASH (26624 * 4)

__global__ void __launch_bounds__(256)
flash_k(const float* __restrict__ qkv, float* __restrict__ ctx) {
    extern __shared__ float sm[];
    const uint32_t s_base = smem_u32(sm);
    int tid = threadIdx.x, lane = tid & 31, warp = tid >> 5;
    int r = lane >> 2, q = lane & 3;
    int bh = blockIdx.y;
    int b = bh >> 4, h = bh & 15;
    int q0 = blockIdx.x * 128;
    int wr = warp * 16;

    const float* Qg = qkv + ((long long)(b * SS + q0)) * (3 * EE) + h * DD;
    const float* Kg = qkv + ((long long)(b * SS)) * (3 * EE) + EE + h * DD;
    const float* Vg = Kg + EE;

    // stage Q into P region
    #pragma unroll
    for (int it = 0; it < 8; ++it) {
        int idx = tid + it * 256;
        int row = idx >> 4, ch = idx & 15;
        cp16(s_base + (uint32_t)((17920 + row * PSTR + ch * 4) * 4),
             Qg + (long long)row * (3 * EE) + ch * 4);
    }
    asm volatile("cp.async.commit_group;");

    auto load_kv = [&](int i, int buf) {
        #pragma unroll
        for (int it = 0; it < 4; ++it) {
            int idx = tid + it * 256;
            int row = idx >> 4, ch = idx & 15;
            cp16(s_base + (uint32_t)((buf * 4352 + row * KSTR + ch * 4) * 4),
                 Kg + (long long)(i * 64 + row) * (3 * EE) + ch * 4);
        }
        #pragma unroll
        for (int it = 0; it < 4; ++it) {
            int idx = tid + it * 256;
            int row = idx >> 4, ch = idx & 15;
            cp16(s_base + (uint32_t)((8704 + buf * 4608 + row * VSTR + ch * 4) * 4),
                 Vg + (long long)(i * 64 + row) * (3 * EE) + ch * 4);
        }
    };
    load_kv(0, 0);
    asm volatile("cp.async.commit_group;");

    // wait for Q only (KV0 still pending), extract fragments
    asm volatile("cp.async.wait_group 1;");
    __syncthreads();
    float* Ps = sm + 17920;
    uint32_t qf[8][4];
    #pragma unroll
    for (int kk = 0; kk < 8; ++kk) {
        const float* p = Ps + (wr + r) * PSTR + kk * 8 + q;
        qf[kk][0] = __float_as_uint(p[0]            * 0.125f);
        qf[kk][1] = __float_as_uint(p[8 * PSTR]     * 0.125f);
        qf[kk][2] = __float_as_uint(p[4]            * 0.125f);
        qf[kk][3] = __float_as_uint(p[8 * PSTR + 4] * 0.125f);
    }
    __syncthreads();   // all warps done reading Q before P writes

    float oacc[8][4];
    #pragma unroll
    for (int nt = 0; nt < 8; ++nt)
        #pragma unroll
        for (int c = 0; c < 4; ++c) oacc[nt][c] = 0.f;
    float m0 = -INFINITY, m1 = -INFINITY, l0 = 0.f, l1 = 0.f;

    for (int i = 0; i < 16; ++i) {
        int buf = i & 1;
        if (i + 1 < 16) {
            load_kv(i + 1, buf ^ 1);
            asm volatile("cp.async.commit_group;");
            asm volatile("cp.async.wait_group 1;");
        } else {
            asm volatile("cp.async.wait_group 0;");
        }
        __syncthreads();

        // S = Qf @ K^T  ([16 x 64] per warp)
        float sacc[8][4];
        #pragma unroll
        for (int nt = 0; nt < 8; ++nt)
            #pragma unroll
            for (int c = 0; c < 4; ++c) sacc[nt][c] = 0.f;
        const uint32_t* ks = reinterpret_cast<const uint32_t*>(sm) + buf * 4352;
        #pragma unroll
        for (int kk = 0; kk < 8; ++kk) {
            uint32_t bf[8][2];
            #pragma unroll
            for (int nt = 0; nt < 8; ++nt) {
                const uint32_t* p = ks + (nt * 8 + r) * KSTR + kk * 8 + q;
                bf[nt][0] = p[0];
                bf[nt][1] = p[4];
            }
            #pragma unroll
            for (int nt = 0; nt < 8; ++nt) mma_tf32(sacc[nt], qf[kk], bf[nt]);
        }

        // online softmax (rows r and r+8; 4 lanes per row, xor 1/2 reduce)
        float mx0 = -INFINITY, mx1 = -INFINITY;
        #pragma unroll
        for (int nt = 0; nt < 8; ++nt) {
            mx0 = fmaxf(mx0, fmaxf(sacc[nt][0], sacc[nt][1]));
            mx1 = fmaxf(mx1, fmaxf(sacc[nt][2], sacc[nt][3]));
        }
        mx0 = fmaxf(mx0, __shfl_xor_sync(~0u, mx0, 1));
        mx0 = fmaxf(mx0, __shfl_xor_sync(~0u, mx0, 2));
        mx1 = fmaxf(mx1, __shfl_xor_sync(~0u, mx1, 1));
        mx1 = fmaxf(mx1, __shfl_xor_sync(~0u, mx1, 2));
        float nm0 = fmaxf(m0, mx0), nm1 = fmaxf(m1, mx1);
        float a0 = __expf(m0 - nm0), a1 = __expf(m1 - nm1);
        m0 = nm0; m1 = nm1;
        float s0 = 0.f, s1 = 0.f;
        #pragma unroll
        for (int nt = 0; nt < 8; ++nt) {
            float e0 = __expf(sacc[nt][0] - m0);
            float e1 = __expf(sacc[nt][1] - m0);
            float e2 = __expf(sacc[nt][2] - m1);
            float e3 = __expf(sacc[nt][3] - m1);
            s0 += e0 + e1; s1 += e2 + e3;
            sacc[nt][0] = rnd_tf32(e0); sacc[nt][1] = rnd_tf32(e1);
            sacc[nt][2] = rnd_tf32(e2); sacc[nt][3] = rnd_tf32(e3);
        }
        s0 += __shfl_xor_sync(~0u, s0, 1); s0 += __shfl_xor_sync(~0u, s0, 2);
        s1 += __shfl_xor_sync(~0u, s1, 1); s1 += __shfl_xor_sync(~0u, s1, 2);
        l0 = l0 * a0 + s0;
        l1 = l1 * a1 + s1;
        #pragma unroll
        for (int nt = 0; nt < 8; ++nt) {
            oacc[nt][0] *= a0; oacc[nt][1] *= a0;
            oacc[nt][2] *= a1; oacc[nt][3] *= a1;
        }

        // write P (C-layout) to warp-private pane, re-read as A fragments
        #pragma unroll
        for (int nt = 0; nt < 8; ++nt) {
            float* pp = Ps + (wr + r) * PSTR + nt * 8 + 2 * q;
            pp[0] = sacc[nt][0]; pp[1] = sacc[nt][1];
            pp[8 * PSTR] = sacc[nt][2]; pp[8 * PSTR + 1] = sacc[nt][3];
        }
        __syncwarp();

        // O += P @ V
        const uint32_t* vs = reinterpret_cast<const uint32_t*>(sm) + 8704 + buf * 4608;
        const uint32_t* pu = reinterpret_cast<const uint32_t*>(Ps);
        #pragma unroll
        for (int kk = 0; kk < 8; ++kk) {
            uint32_t pf[4];
            const uint32_t* pa = pu + (wr + r) * PSTR + kk * 8 + q;
            pf[0] = pa[0];
            pf[1] = pa[8 * PSTR];
            pf[2] = pa[4];
            pf[3] = pa[8 * PSTR + 4];
            #pragma unroll
            for (int nt = 0; nt < 8; ++nt) {
                const uint32_t* p = vs + (kk * 8 + q) * VSTR + nt * 8 + r;
                uint32_t bv2[2] = { p[0], p[4 * VSTR] };
                mma_tf32(oacc[nt], pf, bv2);
            }
        }
        __syncthreads();   // keep warps in lockstep before next buffer overwrite
    }

    // finalize: O /= l, tf32-round, store to ctx [B,S,H,D]
    float inv0 = 1.f / l0, inv1 = 1.f / l1;
    long long grow0 = (long long)(b * SS + q0 + wr + r) * EE + h * DD;
    long long grow1 = grow0 + 8LL * EE;
    #pragma unroll
    for (int nt = 0; nt < 8; ++nt) {
        int col = nt * 8 + 2 * q;
        float2 v0 = make_float2(rnd_tf32(oacc[nt][0] * inv0), rnd_tf32(oacc[nt][1] * inv0));
        float2 v1 = make_float2(rnd_tf32(oacc[nt][2] * inv1), rnd_tf32(oacc[nt][3] * inv1));
        *reinterpret_cast<float2*>(&ctx[grow0 + col]) = v0;
        *reinterpret_cast<float2*>(&ctx[grow1 + col]) = v1;
    }
}

// ---------------- tf32 tensor-core GEMM (operands pre-rounded) --------------
// C = act( A@B (+bias) (+Res) ); BM x BN tile, BK=32, 256 threads.
template<int BM, int BN, int ACT, int ROUND>
__global__ void __launch_bounds__(256)
mma_gemm(const float* __restrict__ A, const float* __restrict__ B,
         const float* __restrict__ bias, const float* __restrict__ Res,
         float* __restrict__ C,
         int K, int lda, int ldb, int ldc) {
    constexpr int BK   = 32;
    constexpr int ASTR = BK + 4;
    constexpr int ASZ  = BM * ASTR;
    constexpr int BSTR = BN + 8;
    constexpr int BSZ  = BK * BSTR;
    constexpr int WM   = BM / 4;
    constexpr int WN   = BN / 2;
    constexpr int MT   = WM / 16;
    constexpr int NT   = WN / 8;
    constexpr int A_CH = BK / 4;
    constexpr int B_CH = BN / 4;
    constexpr int A_IT = (BM * A_CH) / 256;
    constexpr int B_IT = (BK * B_CH) / 256;

    extern __shared__ float sm[];
    const uint32_t s_base = smem_u32(sm);

    int tid  = threadIdx.x;
    int lane = tid & 31;
    int warp = tid >> 5;
    int wm   = (warp & 3) * WM;
    int wn   = (warp >> 2) * WN;
    int m0   = blockIdx.y * BM;
    int n0   = blockIdx.x * BN;
    int r    = lane >> 2;
    int q    = lane & 3;

    float acc[MT][NT][4];
    #pragma unroll
    for (int i = 0; i < MT; ++i)
        #pragma unroll
        for (int j = 0; j < NT; ++j)
            #pragma unroll
            for (int t = 0; t < 4; ++t) acc[i][j][t] = 0.f;

    auto load_tiles = [&](int k0, int buf) {
        #pragma unroll
        for (int it = 0; it < A_IT; ++it) {
            int idx = tid + it * 256;
            int row = idx / A_CH, ch = idx % A_CH;
            cp16(s_base + (uint32_t)((buf * ASZ + row * ASTR + ch * 4) * 4),
                 A + (long long)(m0 + row) * lda + k0 + ch * 4);
        }
        #pragma unroll
        for (int it = 0; it < B_IT; ++it) {
            int idx = tid + it * 256;
            int row = idx / B_CH, ch = idx % B_CH;
            cp16(s_base + (uint32_t)((2 * ASZ + buf * BSZ + row * BSTR + ch * 4) * 4),
                 B + (long long)(k0 + row) * ldb + n0 + ch * 4);
        }
    };

    load_tiles(0, 0);
    asm volatile("cp.async.commit_group;");

    int buf = 0;
    for (int k0 = 0; k0 < K; k0 += BK) {
        asm volatile("cp.async.wait_group 0;");
        __syncthreads();
        if (k0 + BK < K) {
            load_tiles(k0 + BK, buf ^ 1);
            asm volatile("cp.async.commit_group;");
        }
        const uint32_t* as = reinterpret_cast<const uint32_t*>(sm) + buf * ASZ;
        const uint32_t* bs = reinterpret_cast<const uint32_t*>(sm) + 2 * ASZ + buf * BSZ;
        #pragma unroll
        for (int kk = 0; kk < BK / 8; ++kk) {
            uint32_t af[MT][4];
            #pragma unroll
            for (int mt = 0; mt < MT; ++mt) {
                const uint32_t* p = as + (wm + mt * 16 + r) * ASTR + kk * 8 + q;
                af[mt][0] = p[0];
                af[mt][1] = p[8 * ASTR];
                af[mt][2] = p[4];
                af[mt][3] = p[8 * ASTR + 4];
            }
            uint32_t bfr[NT][2];
            #pragma unroll
            for (int nt = 0; nt < NT; ++nt) {
                const uint32_t* p = bs + (kk * 8 + q) * BSTR + wn + nt * 8 + r;
                bfr[nt][0] = p[0];
                bfr[nt][1] = p[4 * BSTR];
            }
            #pragma unroll
            for (int mt = 0; mt < MT; ++mt)
                #pragma unroll
                for (int nt = 0; nt < NT; ++nt)
                    mma_tf32(acc[mt][nt], af[mt], bfr[nt]);
        }
        buf ^= 1;
    }

    #pragma unroll
    for (int mt = 0; mt < MT; ++mt) {
        #pragma unroll
        for (int nt = 0; nt < NT; ++nt) {
            long long row = m0 + wm + mt * 16 + r;
            int col = n0 + wn + nt * 8 + 2 * q;
            float2 v0 = make_float2(acc[mt][nt][0], acc[mt][nt][1]);
            float2 v1 = make_float2(acc[mt][nt][2], acc[mt][nt][3]);
            if (bias) {
                float2 bb = *reinterpret_cast<const float2*>(&bias[col]);
                v0.x += bb.x; v0.y += bb.y; v1.x += bb.x; v1.y += bb.y;
            }
            if (Res) {
                float2 r0 = *reinterpret_cast<const float2*>(&Res[row * ldc + col]);
                float2 r1 = *reinterpret_cast<const float2*>(&Res[(row + 8) * ldc + col]);
                v0.x += r0.x; v0.y += r0.y; v1.x += r1.x; v1.y += r1.y;
            }
            if (ACT == 1) {
                v0.x = 0.5f * v0.x * (1.0f + erff(v0.x * 0.70710678118654752f));
                v0.y = 0.5f * v0.y * (1.0f + erff(v0.y * 0.70710678118654752f));
                v1.x = 0.5f * v1.x * (1.0f + erff(v1.x * 0.70710678118654752f));
                v1.y = 0.5f * v1.y * (1.0f + erff(v1.y * 0.70710678118654752f));
            }
            if (ROUND == 1) {
                v0.x = rnd_tf32(v0.x); v0.y = rnd_tf32(v0.y);
                v1.x = rnd_tf32(v1.x); v1.y = rnd_tf32(v1.y);
            }
            *reinterpret_cast<float2*>(&C[row * ldc + col])       = v0;
            *reinterpret_cast<float2*>(&C[(row + 8) * ldc + col]) = v1;
        }
    }
}

// ---------------- launcher ---------------------------------------------------
extern "C" void kernel_launch(void* const* d_in, const int* in_sizes, int n_in,
                              void* d_out, int out_size) {
    const float* x     = (const float*)d_in[0];
    const float* Wq    = (const float*)d_in[1];
    const float* bq    = (const float*)d_in[2];
    const float* Wk    = (const float*)d_in[3];
    const float* bk    = (const float*)d_in[4];
    const float* Wv    = (const float*)d_in[5];
    const float* bv    = (const float*)d_in[6];
    const float* Wo    = (const float*)d_in[7];
    const float* bo    = (const float*)d_in[8];
    const float* g1    = (const float*)d_in[9];
    const float* beta1 = (const float*)d_in[10];
    const float* g2    = (const float*)d_in[11];
    const float* beta2 = (const float*)d_in[12];
    const float* W1    = (const float*)d_in[13];
    const float* c1    = (const float*)d_in[14];
    const float* W2    = (const float*)d_in[15];
    const float* c2    = (const float*)d_in[16];
    float* out = (float*)d_out;

    float *xn, *qkv, *ctx, *x1, *hb, *Wqkv, *bqkv, *tWo, *tW1, *tW2;
    cudaGetSymbolAddress((void**)&xn,   g_xn);
    cudaGetSymbolAddress((void**)&qkv,  g_qkv);
    cudaGetSymbolAddress((void**)&ctx,  g_ctx);
    cudaGetSymbolAddress((void**)&x1,   g_x1);
    cudaGetSymbolAddress((void**)&hb,   g_h);
    cudaGetSymbolAddress((void**)&Wqkv, g_Wqkv);
    cudaGetSymbolAddress((void**)&bqkv, g_bqkv);
    cudaGetSymbolAddress((void**)&tWo,  g_Wo);
    cudaGetSymbolAddress((void**)&tW1,  g_W1);
    cudaGetSymbolAddress((void**)&tW2,  g_W2);

    const int SM_NT128 = (2 * 128 * 36 + 2 * 32 * 136) * 4;   // 71680

    static bool attr_done = false;
    if (!attr_done) {
        cudaFuncSetAttribute((const void*)mma_gemm<128,128,0,1>,
                             cudaFuncAttributeMaxDynamicSharedMemorySize, SM_NT128);
        cudaFuncSetAttribute((const void*)mma_gemm<128,128,0,0>,
                             cudaFuncAttributeMaxDynamicSharedMemorySize, SM_NT128);
        cudaFuncSetAttribute((const void*)mma_gemm<128,128,1,1>,
                             cudaFuncAttributeMaxDynamicSharedMemorySize, SM_NT128);
        cudaFuncSetAttribute((const void*)flash_k,
                             cudaFuncAttributeMaxDynamicSharedMemorySize, SM_FLASH);
        attr_done = true;
    }

    // 0) one-time-per-replay weight conversions (idempotent, cheap)
    repack_k<<<(HH * EE * DD + 255) / 256, 256>>>(Wq, Wk, Wv, bq, bk, bv, Wqkv, bqkv);
    cvtw_k<<<(EE*EE/4 + 255) / 256, 256>>>(Wo, tWo, EE*EE/4);
    cvtw_k<<<(EE*FFF/4 + 255) / 256, 256>>>(W1, tW1, EE*FFF/4);
    cvtw_k<<<(FFF*EE/4 + 255) / 256, 256>>>(W2, tW2, FFF*EE/4);

    // 1) LN1 (tf32-rounded out)
    layernorm_k<<<MM, 256>>>(x, g1, beta1, xn);

    // 2) fused QKV projection: [8192,1024] x [1024,3072], round out
    mma_gemm<128,128,0,1><<<dim3(3*EE/128, MM/128, 1), 256, SM_NT128>>>(
        xn, Wqkv, bqkv, nullptr, qkv,
        EE, EE, 3*EE, 3*EE);

    // 3) fused flash attention -> ctx (tf32-rounded)
    flash_k<<<dim3(SS/128, BB*HH), 256, SM_FLASH>>>(qkv, ctx);

    // 4) out-proj + bias + residual: x1 = x + ctx @ Wo + bo (f32 out)
    mma_gemm<128,128,0,0><<<dim3(EE/128, MM/128, 1), 256, SM_NT128>>>(
        ctx, tWo, bo, x, x1,
        EE, EE, EE, EE);

    // 5) LN2 (tf32-rounded out)
    layernorm_k<<<MM, 256>>>(x1, g2, beta2, xn);

    // 6) MLP up + exact GELU, round out
    mma_gemm<128,128,1,1><<<dim3(FFF/128, MM/128, 1), 256, SM_NT128>>>(
        xn, tW1, c1, nullptr, hb,
        EE, EE, FFF, FFF);

    // 7) MLP down + bias + residual -> d_out (f32)
    mma_gemm<128,128,0,0><<<dim3(EE/128, MM/128, 1), 256, SM_NT128>>>(
        hb, tW2, c2, x1, out,
        FFF, FFF, EE, EE);
}

// round 6
// speedup vs baseline: 6.5407x; 1.7266x over previous
#include <cuda_runtime.h>
#include <cuda_fp16.h>
#include <math.h>
#include <stdint.h>

// Problem constants
#define BB  8
#define SS  1024
#define EE  1024
#define HH  16
#define DD  64
#define FFF 4096
#define MM  (BB*SS)          // 8192 rows

// ---------------- scratch (static device globals; no cudaMalloc allowed) ----
__device__ __half g_xn  [(long long)MM*EE];        // fp16 LN outputs
__device__ __half g_qkv [(long long)MM*3*EE];      // fp16 q/k/v
__device__ __half g_ctx [(long long)MM*EE];        // fp16 attention out
__device__ float  g_x1  [(long long)MM*EE];        // f32 residual stream
__device__ __half g_h   [(long long)MM*FFF];       // fp16 MLP hidden
__device__ __half g_Wqkv[(long long)EE*3*EE];      // W_qkv^T [3E, E] fp16
__device__ float  g_bqkv[3*EE];
__device__ __half g_Wo  [(long long)EE*EE];        // Wo^T [E,E] fp16
__device__ __half g_W1  [(long long)EE*FFF];       // W1^T [FF,E] fp16
__device__ __half g_W2  [(long long)FFF*EE];       // W2^T [E,FF] fp16

__device__ __forceinline__ uint32_t smem_u32(const void* p) {
    uint32_t a;
    asm("{ .reg .u64 t; cvta.to.shared.u64 t, %1; cvt.u32.u64 %0, t; }" : "=r"(a) : "l"(p));
    return a;
}
__device__ __forceinline__ void cp16(uint32_t dst, const void* src) {
    asm volatile("cp.async.cg.shared.global [%0], [%1], 16;" :: "r"(dst), "l"(src));
}
__device__ __forceinline__ void mma_f16(float* d, const uint32_t* a, const uint32_t* b) {
    asm volatile(
        "mma.sync.aligned.m16n8k16.row.col.f32.f16.f16.f32 "
        "{%0,%1,%2,%3}, {%4,%5,%6,%7}, {%8,%9}, {%0,%1,%2,%3};"
        : "+f"(d[0]), "+f"(d[1]), "+f"(d[2]), "+f"(d[3])
        : "r"(a[0]), "r"(a[1]), "r"(a[2]), "r"(a[3]), "r"(b[0]), "r"(b[1]));
}
__device__ __forceinline__ uint32_t packh2(float a, float b) {
    __half2 h = __floats2half2_rn(a, b);
    return *reinterpret_cast<uint32_t*>(&h);
}

// ---------------- prep: Wq/Wk/Wv [H,E,D] -> Wqkv^T [3E, E] (fp16) ----------
__global__ void repack_t_k(const float* __restrict__ Wq, const float* __restrict__ Wk,
                           const float* __restrict__ Wv,
                           const float* __restrict__ bq, const float* __restrict__ bk,
                           const float* __restrict__ bv,
                           __half* __restrict__ Wt, float* __restrict__ bqkv) {
    int idx = blockIdx.x * blockDim.x + threadIdx.x;
    const int total = HH * EE * DD;
    if (idx < total) {
        int h = idx / (DD * EE);
        int d = (idx / EE) % DD;
        int e = idx % EE;
        int col = h * DD + d;
        long long src = (long long)h * EE * DD + (long long)e * DD + d;
        Wt[(long long)col * EE + e]            = __float2half_rn(Wq[src]);
        Wt[(long long)(EE + col) * EE + e]     = __float2half_rn(Wk[src]);
        Wt[(long long)(2 * EE + col) * EE + e] = __float2half_rn(Wv[src]);
    }
    if (idx < EE) {
        bqkv[idx]          = bq[idx];
        bqkv[EE + idx]     = bk[idx];
        bqkv[2 * EE + idx] = bv[idx];
    }
}

// ---------------- prep: transpose + fp16-round: src[R,C] -> dst[C,R] --------
__global__ void transp_k(const float* __restrict__ src, __half* __restrict__ dst,
                         int R, int Ccols) {
    __shared__ float t[32][33];
    int c0 = blockIdx.x * 32, r0 = blockIdx.y * 32;
    for (int i = threadIdx.y; i < 32; i += 8)
        t[i][threadIdx.x] = src[(long long)(r0 + i) * Ccols + c0 + threadIdx.x];
    __syncthreads();
    for (int i = threadIdx.y; i < 32; i += 8)
        dst[(long long)(c0 + i) * R + r0 + threadIdx.x] = __float2half_rn(t[threadIdx.x][i]);
}

// ---------------- layernorm (fp16 out) ---------------------------------------
__global__ void layernorm_k(const float* __restrict__ x, const float* __restrict__ g,
                            const float* __restrict__ b, __half* __restrict__ y) {
    const float4* px = reinterpret_cast<const float4*>(x) + (long long)blockIdx.x * 256;
    uint2*        py = reinterpret_cast<uint2*>(y)        + (long long)blockIdx.x * 256;
    int tid = threadIdx.x;
    float4 v = px[tid];
    float s  = v.x + v.y + v.z + v.w;
    float sq = v.x*v.x + v.y*v.y + v.z*v.z + v.w*v.w;
    __shared__ float rs[8], rq[8];
    #pragma unroll
    for (int o = 16; o; o >>= 1) {
        s  += __shfl_xor_sync(~0u, s,  o);
        sq += __shfl_xor_sync(~0u, sq, o);
    }
    if ((tid & 31) == 0) { rs[tid >> 5] = s; rq[tid >> 5] = sq; }
    __syncthreads();
    float ts = 0.f, tq = 0.f;
    #pragma unroll
    for (int i = 0; i < 8; ++i) { ts += rs[i]; tq += rq[i]; }
    float mean = ts * (1.0f / EE);
    float var  = tq * (1.0f / EE) - mean * mean;
    float inv  = rsqrtf(var + 1e-5f);
    float4 gv = reinterpret_cast<const float4*>(g)[tid];
    float4 bv = reinterpret_cast<const float4*>(b)[tid];
    uint2 u;
    u.x = packh2((v.x - mean) * inv * gv.x + bv.x, (v.y - mean) * inv * gv.y + bv.y);
    u.y = packh2((v.z - mean) * inv * gv.z + bv.z, (v.w - mean) * inv * gv.w + bv.w);
    py[tid] = u;
}

// ---------------- fused flash attention (fp16 operands) ----------------------
// grid (S/128, B*H), 256 threads (8 warps); each warp owns 16 Q rows.
// smem halves: K[2][64][72] @0, V[2][64][72] @9216, Q[128][72] @18432.
#define HSTR 72
#define SM_FLASH (27648 * 2)

__global__ void __launch_bounds__(256)
flash_k(const __half* __restrict__ qkv, __half* __restrict__ ctx) {
    extern __shared__ char smraw[];
    __half* sm = reinterpret_cast<__half*>(smraw);
    const uint32_t s_base = smem_u32(sm);
    int tid = threadIdx.x, lane = tid & 31, warp = tid >> 5;
    int r = lane >> 2, q = lane & 3;
    int bh = blockIdx.y;
    int b = bh >> 4, h = bh & 15;
    int q0 = blockIdx.x * 128;
    int wr = warp * 16;

    const __half* Qg = qkv + ((long long)(b * SS + q0)) * (3 * EE) + h * DD;
    const __half* Kg = qkv + ((long long)(b * SS)) * (3 * EE) + EE + h * DD;
    const __half* Vg = Kg + EE;

    // stage Q [128 x 64]
    #pragma unroll
    for (int it = 0; it < 4; ++it) {
        int idx = tid + it * 256;
        int row = idx >> 3, ch = idx & 7;
        cp16(s_base + (uint32_t)((18432 + row * HSTR + ch * 8) * 2),
             Qg + (long long)row * (3 * EE) + ch * 8);
    }
    asm volatile("cp.async.commit_group;");

    auto load_kv = [&](int i, int buf) {
        #pragma unroll
        for (int it = 0; it < 2; ++it) {
            int idx = tid + it * 256;
            int row = idx >> 3, ch = idx & 7;
            cp16(s_base + (uint32_t)((buf * 4608 + row * HSTR + ch * 8) * 2),
                 Kg + (long long)(i * 64 + row) * (3 * EE) + ch * 8);
        }
        #pragma unroll
        for (int it = 0; it < 2; ++it) {
            int idx = tid + it * 256;
            int row = idx >> 3, ch = idx & 7;
            cp16(s_base + (uint32_t)((9216 + buf * 4608 + row * HSTR + ch * 8) * 2),
                 Vg + (long long)(i * 64 + row) * (3 * EE) + ch * 8);
        }
    };
    load_kv(0, 0);
    asm volatile("cp.async.commit_group;");

    // wait for Q, build fp16 fragments (scaled by 0.125 — exact)
    asm volatile("cp.async.wait_group 1;");
    __syncthreads();
    const uint32_t* Qsu = reinterpret_cast<const uint32_t*>(sm) + 9216;  // uint32 units
    const __half2 s8 = __float2half2_rn(0.125f);
    uint32_t qf[4][4];
    #pragma unroll
    for (int kk = 0; kk < 4; ++kk) {
        int base = (wr + r) * 36 + kk * 8 + q;
        uint32_t u0 = Qsu[base];
        uint32_t u1 = Qsu[base + 8 * 36];
        uint32_t u2 = Qsu[base + 4];
        uint32_t u3 = Qsu[base + 8 * 36 + 4];
        __half2 h0 = __hmul2(*reinterpret_cast<__half2*>(&u0), s8);
        __half2 h1 = __hmul2(*reinterpret_cast<__half2*>(&u1), s8);
        __half2 h2 = __hmul2(*reinterpret_cast<__half2*>(&u2), s8);
        __half2 h3 = __hmul2(*reinterpret_cast<__half2*>(&u3), s8);
        qf[kk][0] = *reinterpret_cast<uint32_t*>(&h0);
        qf[kk][1] = *reinterpret_cast<uint32_t*>(&h1);
        qf[kk][2] = *reinterpret_cast<uint32_t*>(&h2);
        qf[kk][3] = *reinterpret_cast<uint32_t*>(&h3);
    }

    float oacc[8][4];
    #pragma unroll
    for (int nt = 0; nt < 8; ++nt)
        #pragma unroll
        for (int c = 0; c < 4; ++c) oacc[nt][c] = 0.f;
    float m0 = -INFINITY, m1 = -INFINITY, l0 = 0.f, l1 = 0.f;

    for (int i = 0; i < 16; ++i) {
        int buf = i & 1;
        if (i + 1 < 16) {
            load_kv(i + 1, buf ^ 1);
            asm volatile("cp.async.commit_group;");
            asm volatile("cp.async.wait_group 1;");
        } else {
            asm volatile("cp.async.wait_group 0;");
        }
        __syncthreads();

        // S = Q @ K^T : [16 x 64] per warp; K rows are key positions (n-dim)
        float sacc[8][4];
        #pragma unroll
        for (int nt = 0; nt < 8; ++nt)
            #pragma unroll
            for (int c = 0; c < 4; ++c) sacc[nt][c] = 0.f;
        const uint32_t* Ksu = reinterpret_cast<const uint32_t*>(sm) + buf * 2304;
        #pragma unroll
        for (int kk = 0; kk < 4; ++kk) {
            #pragma unroll
            for (int nt = 0; nt < 8; ++nt) {
                int base = (nt * 8 + r) * 36 + kk * 8 + q;
                uint32_t bf[2] = { Ksu[base], Ksu[base + 4] };
                mma_f16(sacc[nt], qf[kk], bf);
            }
        }

        // online softmax (rows r, r+8; 4 lanes per row)
        float mx0 = -INFINITY, mx1 = -INFINITY;
        #pragma unroll
        for (int nt = 0; nt < 8; ++nt) {
            mx0 = fmaxf(mx0, fmaxf(sacc[nt][0], sacc[nt][1]));
            mx1 = fmaxf(mx1, fmaxf(sacc[nt][2], sacc[nt][3]));
        }
        mx0 = fmaxf(mx0, __shfl_xor_sync(~0u, mx0, 1));
        mx0 = fmaxf(mx0, __shfl_xor_sync(~0u, mx0, 2));
        mx1 = fmaxf(mx1, __shfl_xor_sync(~0u, mx1, 1));
        mx1 = fmaxf(mx1, __shfl_xor_sync(~0u, mx1, 2));
        float nm0 = fmaxf(m0, mx0), nm1 = fmaxf(m1, mx1);
        float a0 = __expf(m0 - nm0), a1 = __expf(m1 - nm1);
        m0 = nm0; m1 = nm1;
        float s0 = 0.f, s1 = 0.f;
        #pragma unroll
        for (int nt = 0; nt < 8; ++nt) {
            sacc[nt][0] = __expf(sacc[nt][0] - m0);
            sacc[nt][1] = __expf(sacc[nt][1] - m0);
            sacc[nt][2] = __expf(sacc[nt][2] - m1);
            sacc[nt][3] = __expf(sacc[nt][3] - m1);
            s0 += sacc[nt][0] + sacc[nt][1];
            s1 += sacc[nt][2] + sacc[nt][3];
        }
        s0 += __shfl_xor_sync(~0u, s0, 1); s0 += __shfl_xor_sync(~0u, s0, 2);
        s1 += __shfl_xor_sync(~0u, s1, 1); s1 += __shfl_xor_sync(~0u, s1, 2);
        l0 = l0 * a0 + s0;
        l1 = l1 * a1 + s1;
        #pragma unroll
        for (int nt = 0; nt < 8; ++nt) {
            oacc[nt][0] *= a0; oacc[nt][1] *= a0;
            oacc[nt][2] *= a1; oacc[nt][3] *= a1;
        }

        // O += P @ V ; P comes straight from sacc registers (fp16 pack),
        // V via ldmatrix.x4.trans.b16
        int mi = lane >> 3, rowin = lane & 7;
        #pragma unroll
        for (int kk = 0; kk < 4; ++kk) {
            uint32_t pf[4];
            pf[0] = packh2(sacc[2*kk][0],   sacc[2*kk][1]);
            pf[1] = packh2(sacc[2*kk][2],   sacc[2*kk][3]);
            pf[2] = packh2(sacc[2*kk+1][0], sacc[2*kk+1][1]);
            pf[3] = packh2(sacc[2*kk+1][2], sacc[2*kk+1][3]);
            #pragma unroll
            for (int nbp = 0; nbp < 4; ++nbp) {
                uint32_t vaddr = s_base +
                    (uint32_t)((9216 + buf * 4608 +
                                (kk * 16 + ((mi & 1) << 3) + rowin) * HSTR +
                                nbp * 16 + ((mi >> 1) << 3)) * 2);
                uint32_t d0, d1, d2, d3;
                asm volatile(
                    "ldmatrix.sync.aligned.m8n8.x4.trans.shared.b16 {%0,%1,%2,%3}, [%4];"
                    : "=r"(d0), "=r"(d1), "=r"(d2), "=r"(d3) : "r"(vaddr));
                uint32_t bA[2] = { d0, d1 };
                uint32_t bB[2] = { d2, d3 };
                mma_f16(oacc[2*nbp],     pf, bA);
                mma_f16(oacc[2*nbp + 1], pf, bB);
            }
        }
        __syncthreads();
    }

    float inv0 = 1.f / l0, inv1 = 1.f / l1;
    long long grow0 = (long long)(b * SS + q0 + wr + r) * EE + h * DD;
    long long grow1 = grow0 + 8LL * EE;
    #pragma unroll
    for (int nt = 0; nt < 8; ++nt) {
        int col = nt * 8 + 2 * q;
        *reinterpret_cast<uint32_t*>(&ctx[grow0 + col]) =
            packh2(oacc[nt][0] * inv0, oacc[nt][1] * inv0);
        *reinterpret_cast<uint32_t*>(&ctx[grow1 + col]) =
            packh2(oacc[nt][2] * inv1, oacc[nt][3] * inv1);
    }
}

// ---------------- fp16 tensor-core GEMM --------------------------------------
// C[M,N] = act( A[M,K] @ Bt[N,K]^T (+bias) (+Res) ); 128x128 tile, BK=64,
// 256 threads (8 warps 4x2), double-buffered cp.async.
// OUTH: 1 -> write __half C, 0 -> write float C.
#define GSTR 72                    // halves per smem row
#define SM_DENSE (36864 * 2)       // 4 tiles of 128x72 halves

template<int ACT, int OUTH>
__global__ void __launch_bounds__(256)
mma_gemm(const __half* __restrict__ A, const __half* __restrict__ Bt,
         const float* __restrict__ bias, const float* __restrict__ Res,
         void* __restrict__ Cv, int K, int ldc) {
    extern __shared__ char smraw[];
    __half* sm = reinterpret_cast<__half*>(smraw);
    const uint32_t s_base = smem_u32(sm);

    int tid  = threadIdx.x;
    int lane = tid & 31;
    int warp = tid >> 5;
    int wm   = (warp & 3) * 32;
    int wn   = (warp >> 2) * 64;
    int m0   = blockIdx.y * 128;
    int n0   = blockIdx.x * 128;
    int r    = lane >> 2;
    int q    = lane & 3;

    float acc[2][8][4];
    #pragma unroll
    for (int i = 0; i < 2; ++i)
        #pragma unroll
        for (int j = 0; j < 8; ++j)
            #pragma unroll
            for (int t = 0; t < 4; ++t) acc[i][j][t] = 0.f;

    // smem layout (halves): A[buf] at buf*9216, B[buf] at 18432 + buf*9216
    auto load_tiles = [&](int k0, int buf) {
        #pragma unroll
        for (int it = 0; it < 4; ++it) {
            int idx = tid + it * 256;
            int row = idx >> 3, ch = idx & 7;
            cp16(s_base + (uint32_t)((buf * 9216 + row * GSTR + ch * 8) * 2),
                 A + (long long)(m0 + row) * K + k0 + ch * 8);
        }
        #pragma unroll
        for (int it = 0; it < 4; ++it) {
            int idx = tid + it * 256;
            int row = idx >> 3, ch = idx & 7;
            cp16(s_base + (uint32_t)((18432 + buf * 9216 + row * GSTR + ch * 8) * 2),
                 Bt + (long long)(n0 + row) * K + k0 + ch * 8);
        }
    };

    load_tiles(0, 0);
    asm volatile("cp.async.commit_group;");

    int buf = 0;
    for (int k0 = 0; k0 < K; k0 += 64) {
        asm volatile("cp.async.wait_group 0;");
        __syncthreads();
        if (k0 + 64 < K) {
            load_tiles(k0 + 64, buf ^ 1);
            asm volatile("cp.async.commit_group;");
        }
        const uint32_t* asu = reinterpret_cast<const uint32_t*>(sm) + buf * 4608;
        const uint32_t* bsu = reinterpret_cast<const uint32_t*>(sm) + 9216 + buf * 4608;
        #pragma unroll
        for (int kk = 0; kk < 4; ++kk) {
            uint32_t af[2][4];
            #pragma unroll
            for (int mt = 0; mt < 2; ++mt) {
                int base = (wm + mt * 16 + r) * 36 + kk * 8 + q;
                af[mt][0] = asu[base];
                af[mt][1] = asu[base + 8 * 36];
                af[mt][2] = asu[base + 4];
                af[mt][3] = asu[base + 8 * 36 + 4];
            }
            #pragma unroll
            for (int nt = 0; nt < 8; ++nt) {
                int base = (wn + nt * 8 + r) * 36 + kk * 8 + q;
                uint32_t bf[2] = { bsu[base], bsu[base + 4] };
                #pragma unroll
                for (int mt = 0; mt < 2; ++mt)
                    mma_f16(acc[mt][nt], af[mt], bf);
            }
        }
        buf ^= 1;
    }

    #pragma unroll
    for (int mt = 0; mt < 2; ++mt) {
        #pragma unroll
        for (int nt = 0; nt < 8; ++nt) {
            long long row = m0 + wm + mt * 16 + r;
            int col = n0 + wn + nt * 8 + 2 * q;
            float2 v0 = make_float2(acc[mt][nt][0], acc[mt][nt][1]);
            float2 v1 = make_float2(acc[mt][nt][2], acc[mt][nt][3]);
            if (bias) {
                float2 bb = *reinterpret_cast<const float2*>(&bias[col]);
                v0.x += bb.x; v0.y += bb.y; v1.x += bb.x; v1.y += bb.y;
            }
            if (Res) {
                float2 r0 = *reinterpret_cast<const float2*>(&Res[row * ldc + col]);
                float2 r1 = *reinterpret_cast<const float2*>(&Res[(row + 8) * ldc + col]);
                v0.x += r0.x; v0.y += r0.y; v1.x += r1.x; v1.y += r1.y;
            }
            if (ACT == 1) {
                v0.x = 0.5f * v0.x * (1.0f + erff(v0.x * 0.70710678118654752f));
                v0.y = 0.5f * v0.y * (1.0f + erff(v0.y * 0.70710678118654752f));
                v1.x = 0.5f * v1.x * (1.0f + erff(v1.x * 0.70710678118654752f));
                v1.y = 0.5f * v1.y * (1.0f + erff(v1.y * 0.70710678118654752f));
            }
            if (OUTH) {
                __half* C = reinterpret_cast<__half*>(Cv);
                *reinterpret_cast<uint32_t*>(&C[row * ldc + col])       = packh2(v0.x, v0.y);
                *reinterpret_cast<uint32_t*>(&C[(row + 8) * ldc + col]) = packh2(v1.x, v1.y);
            } else {
                float* C = reinterpret_cast<float*>(Cv);
                *reinterpret_cast<float2*>(&C[row * ldc + col])       = v0;
                *reinterpret_cast<float2*>(&C[(row + 8) * ldc + col]) = v1;
            }
        }
    }
}

// ---------------- launcher ---------------------------------------------------
extern "C" void kernel_launch(void* const* d_in, const int* in_sizes, int n_in,
                              void* d_out, int out_size) {
    const float* x     = (const float*)d_in[0];
    const float* Wq    = (const float*)d_in[1];
    const float* bq    = (const float*)d_in[2];
    const float* Wk    = (const float*)d_in[3];
    const float* bk    = (const float*)d_in[4];
    const float* Wv    = (const float*)d_in[5];
    const float* bv    = (const float*)d_in[6];
    const float* Wo    = (const float*)d_in[7];
    const float* bo    = (const float*)d_in[8];
    const float* g1    = (const float*)d_in[9];
    const float* beta1 = (const float*)d_in[10];
    const float* g2    = (const float*)d_in[11];
    const float* beta2 = (const float*)d_in[12];
    const float* W1    = (const float*)d_in[13];
    const float* c1    = (const float*)d_in[14];
    const float* W2    = (const float*)d_in[15];
    const float* c2    = (const float*)d_in[16];
    float* out = (float*)d_out;

    __half *xn, *qkv, *ctx, *hb, *Wqkvt, *tWo, *tW1, *tW2;
    float *x1, *bqkv;
    cudaGetSymbolAddress((void**)&xn,    g_xn);
    cudaGetSymbolAddress((void**)&qkv,   g_qkv);
    cudaGetSymbolAddress((void**)&ctx,   g_ctx);
    cudaGetSymbolAddress((void**)&x1,    g_x1);
    cudaGetSymbolAddress((void**)&hb,    g_h);
    cudaGetSymbolAddress((void**)&Wqkvt, g_Wqkv);
    cudaGetSymbolAddress((void**)&bqkv,  g_bqkv);
    cudaGetSymbolAddress((void**)&tWo,   g_Wo);
    cudaGetSymbolAddress((void**)&tW1,   g_W1);
    cudaGetSymbolAddress((void**)&tW2,   g_W2);

    static bool attr_done = false;
    if (!attr_done) {
        cudaFuncSetAttribute((const void*)mma_gemm<0,1>,
                             cudaFuncAttributeMaxDynamicSharedMemorySize, SM_DENSE);
        cudaFuncSetAttribute((const void*)mma_gemm<0,0>,
                             cudaFuncAttributeMaxDynamicSharedMemorySize, SM_DENSE);
        cudaFuncSetAttribute((const void*)mma_gemm<1,1>,
                             cudaFuncAttributeMaxDynamicSharedMemorySize, SM_DENSE);
        cudaFuncSetAttribute((const void*)flash_k,
                             cudaFuncAttributeMaxDynamicSharedMemorySize, SM_FLASH);
        attr_done = true;
    }

    // 0) weight prep: transposed + fp16 copies
    repack_t_k<<<(HH * EE * DD + 255) / 256, 256>>>(Wq, Wk, Wv, bq, bk, bv, Wqkvt, bqkv);
    transp_k<<<dim3(EE/32,  EE/32),  dim3(32, 8)>>>(Wo, tWo, EE,  EE);
    transp_k<<<dim3(FFF/32, EE/32),  dim3(32, 8)>>>(W1, tW1, EE,  FFF);
    transp_k<<<dim3(EE/32,  FFF/32), dim3(32, 8)>>>(W2, tW2, FFF, EE);

    // 1) LN1 -> fp16
    layernorm_k<<<MM, 256>>>(x, g1, beta1, xn);

    // 2) QKV projection: [8192,1024] x [1024,3072] -> fp16
    mma_gemm<0,1><<<dim3(3*EE/128, MM/128), 256, SM_DENSE>>>(
        xn, Wqkvt, bqkv, nullptr, qkv, EE, 3*EE);

    // 3) flash attention -> ctx (fp16)
    flash_k<<<dim3(SS/128, BB*HH), 256, SM_FLASH>>>(qkv, ctx);

    // 4) out-proj + bias + residual -> x1 (f32)
    mma_gemm<0,0><<<dim3(EE/128, MM/128), 256, SM_DENSE>>>(
        ctx, tWo, bo, x, x1, EE, EE);

    // 5) LN2 -> fp16
    layernorm_k<<<MM, 256>>>(x1, g2, beta2, xn);

    // 6) MLP up + exact GELU -> fp16
    mma_gemm<1,1><<<dim3(FFF/128, MM/128), 256, SM_DENSE>>>(
        xn, tW1, c1, nullptr, hb, EE, FFF);

    // 7) MLP down + bias + residual -> d_out (f32)
    mma_gemm<0,0><<<dim3(EE/128, MM/128), 256, SM_DENSE>>>(
        hb, tW2, c2, x1, out, FFF, EE);
}